// round 1
// baseline (speedup 1.0000x reference)
#include <cuda_runtime.h>
#include <math.h>

// Problem constants
#define S_LEN 4096
#define D_DIM 1024
#define NH    16
#define HDIM  64
#define FF_D  4096

// ---------------- scratch (device globals: allocation-free rule) ----------------
__device__ float g_y  [S_LEN * D_DIM];            // LN output (reused for LN1 and LN2)
__device__ float g_q  [S_LEN * D_DIM];
__device__ float g_k  [S_LEN * D_DIM];
__device__ float g_v  [S_LEN * D_DIM];
__device__ float g_o  [S_LEN * D_DIM];            // attention output (S, H*HD)
__device__ float g_x1 [S_LEN * D_DIM];            // x + attn_out
__device__ float g_ffn[S_LEN * FF_D];             // gelu(y@W1+b1)
__device__ float g_scores[268435456];             // 16 * 4096 * 4096 (1 GB)

// ---------------- LayerNorm ----------------
__global__ __launch_bounds__(256) void ln_kernel(const float* __restrict__ x,
                                                 const float* __restrict__ sc,
                                                 const float* __restrict__ bi,
                                                 float* __restrict__ y)
{
    long long row = blockIdx.x;
    const float* xr = x + row * D_DIM;
    int c = threadIdx.x << 2;                       // 256 threads * 4 = 1024 cols
    float4 xv = *(const float4*)(xr + c);
    float s  = xv.x + xv.y + xv.z + xv.w;
    float ss = xv.x*xv.x + xv.y*xv.y + xv.z*xv.z + xv.w*xv.w;
    #pragma unroll
    for (int off = 16; off; off >>= 1) {
        s  += __shfl_down_sync(0xffffffffu, s,  off);
        ss += __shfl_down_sync(0xffffffffu, ss, off);
    }
    __shared__ float sbuf[8], ssbuf[8];
    __shared__ float mu_s, rinv_s;
    int w = threadIdx.x >> 5, l = threadIdx.x & 31;
    if (l == 0) { sbuf[w] = s; ssbuf[w] = ss; }
    __syncthreads();
    if (threadIdx.x == 0) {
        float S = 0.f, SS = 0.f;
        #pragma unroll
        for (int i = 0; i < 8; i++) { S += sbuf[i]; SS += ssbuf[i]; }
        float mu  = S * (1.0f / D_DIM);
        float var = SS * (1.0f / D_DIM) - mu * mu;
        mu_s = mu;
        rinv_s = rsqrtf(var + 1e-6f);
    }
    __syncthreads();
    float mu = mu_s, rinv = rinv_s;
    float4 scv = *(const float4*)(sc + c);
    float4 bv  = *(const float4*)(bi + c);
    float4 ov;
    ov.x = (xv.x - mu) * rinv * scv.x + bv.x;
    ov.y = (xv.y - mu) * rinv * scv.y + bv.y;
    ov.z = (xv.z - mu) * rinv * scv.z + bv.z;
    ov.w = (xv.w - mu) * rinv * scv.w + bv.w;
    *(float4*)(y + row * D_DIM + c) = ov;
}

// ---------------- RoPE (in place, layout (S, H, HD)) ----------------
__global__ void rope_kernel(float* __restrict__ buf)
{
    int c = threadIdx.x;                 // 0..31 (half of head dim)
    int s = blockIdx.x;                  // token
    int h = blockIdx.y;                  // head
    float* p = buf + (long long)s * D_DIM + h * HDIM;
    // freq = 10000^(-c/32)
    float freq = expf(-(float)c * (9.210340371976184f / 32.0f));
    float ang = (float)s * freq;
    float sn, cs;
    sincosf(ang, &sn, &cs);
    float x1 = p[c], x2 = p[c + 32];
    p[c]      = x1 * cs - x2 * sn;
    p[c + 32] = x2 * cs + x1 * sn;
}

// ---------------- row softmax over 4096 cols (in place, with scale) ----------------
__global__ __launch_bounds__(256) void softmax_kernel(float* __restrict__ scores, float scale)
{
    long long row = blockIdx.x;
    float* p = scores + row * S_LEN;
    float vals[16];
    float m = -3.4e38f;
    #pragma unroll
    for (int j = 0; j < 16; j++) {
        float v = p[threadIdx.x + j * 256] * scale;
        vals[j] = v;
        m = fmaxf(m, v);
    }
    #pragma unroll
    for (int off = 16; off; off >>= 1) m = fmaxf(m, __shfl_xor_sync(0xffffffffu, m, off));
    __shared__ float redm[8], reds[8];
    int w = threadIdx.x >> 5, l = threadIdx.x & 31;
    if (l == 0) redm[w] = m;
    __syncthreads();
    m = redm[0];
    #pragma unroll
    for (int i = 1; i < 8; i++) m = fmaxf(m, redm[i]);

    float sum = 0.f;
    #pragma unroll
    for (int j = 0; j < 16; j++) {
        float e = expf(vals[j] - m);
        vals[j] = e;
        sum += e;
    }
    #pragma unroll
    for (int off = 16; off; off >>= 1) sum += __shfl_xor_sync(0xffffffffu, sum, off);
    if (l == 0) reds[w] = sum;
    __syncthreads();
    sum = 0.f;
    #pragma unroll
    for (int i = 0; i < 8; i++) sum += reds[i];
    float rs = 1.0f / sum;
    #pragma unroll
    for (int j = 0; j < 16; j++) p[threadIdx.x + j * 256] = vals[j] * rs;
}

// ---------------- tiled fp32 GEMM, 64x64x16, 256 threads, 4x4 microtile ----------------
// C(z) = A(z)[M,K] * op(B(z)) (+bias over cols) (+resid same layout as C) (gelu)
// BT=false: B is K x N row-major (ldb).  BT=true: B is N x K row-major (ldb).
// All of M, N multiples of 64; K multiple of 16 (true for every call site here).
#define EPI_NONE      0
#define EPI_BIAS      1
#define EPI_BIAS_RES  2
#define EPI_BIAS_GELU 3

__device__ __forceinline__ float gelu_exact(float v)
{
    return 0.5f * v * (1.0f + erff(v * 0.70710678118654752f));
}

template<bool BT>
__global__ __launch_bounds__(256) void gemm64(
    const float* __restrict__ A, int lda, long long strA,
    const float* __restrict__ B, int ldb, long long strB,
    float* __restrict__ C, int ldc, long long strC,
    int K,
    const float* __restrict__ bias,
    const float* __restrict__ resid,
    int epi)
{
    __shared__ float As[16][64];
    __shared__ float Bs[16][64];

    A += strA * blockIdx.z;
    B += strB * blockIdx.z;
    C += strC * blockIdx.z;

    const int m0 = blockIdx.y << 6;
    const int n0 = blockIdx.x << 6;
    const int tid = threadIdx.x;
    const int tx = tid & 15, ty = tid >> 4;
    const int ar = tid >> 2;               // 0..63
    const int ac = (tid & 3) << 2;         // 0,4,8,12
    const int br = tid >> 4;               // 0..15
    const int bc = (tid & 15) << 2;        // 0..60

    const float* Ap = A + (long long)(m0 + ar) * lda + ac;
    const float* Bp = BT ? (B + (long long)(n0 + ar) * ldb + ac)
                         : (B + (long long)br * ldb + n0 + bc);

    float acc[4][4] = {};

    for (int k0 = 0; k0 < K; k0 += 16) {
        float4 a = *(const float4*)(Ap + k0);
        As[ac + 0][ar] = a.x; As[ac + 1][ar] = a.y;
        As[ac + 2][ar] = a.z; As[ac + 3][ar] = a.w;
        if (BT) {
            float4 b = *(const float4*)(Bp + k0);
            Bs[ac + 0][ar] = b.x; Bs[ac + 1][ar] = b.y;
            Bs[ac + 2][ar] = b.z; Bs[ac + 3][ar] = b.w;
        } else {
            float4 b = *(const float4*)(Bp + (long long)k0 * ldb);
            *(float4*)&Bs[br][bc] = b;
        }
        __syncthreads();
        #pragma unroll
        for (int kk = 0; kk < 16; kk++) {
            float4 av = *(const float4*)&As[kk][ty << 2];
            float4 bv = *(const float4*)&Bs[kk][tx << 2];
            acc[0][0] += av.x * bv.x; acc[0][1] += av.x * bv.y;
            acc[0][2] += av.x * bv.z; acc[0][3] += av.x * bv.w;
            acc[1][0] += av.y * bv.x; acc[1][1] += av.y * bv.y;
            acc[1][2] += av.y * bv.z; acc[1][3] += av.y * bv.w;
            acc[2][0] += av.z * bv.x; acc[2][1] += av.z * bv.y;
            acc[2][2] += av.z * bv.z; acc[2][3] += av.z * bv.w;
            acc[3][0] += av.w * bv.x; acc[3][1] += av.w * bv.y;
            acc[3][2] += av.w * bv.z; acc[3][3] += av.w * bv.w;
        }
        __syncthreads();
    }

    const int cc = n0 + (tx << 2);
    float4 bb = make_float4(0.f, 0.f, 0.f, 0.f);
    if (epi != EPI_NONE) bb = *(const float4*)(bias + cc);

    #pragma unroll
    for (int i = 0; i < 4; i++) {
        int r = m0 + (ty << 2) + i;
        float4 ov = make_float4(acc[i][0] + bb.x, acc[i][1] + bb.y,
                                acc[i][2] + bb.z, acc[i][3] + bb.w);
        if (epi == EPI_BIAS_RES) {
            float4 rr = *(const float4*)(resid + (long long)r * ldc + cc);
            ov.x += rr.x; ov.y += rr.y; ov.z += rr.z; ov.w += rr.w;
        } else if (epi == EPI_BIAS_GELU) {
            ov.x = gelu_exact(ov.x); ov.y = gelu_exact(ov.y);
            ov.z = gelu_exact(ov.z); ov.w = gelu_exact(ov.w);
        }
        *(float4*)(C + (long long)r * ldc + cc) = ov;
    }
}

// ---------------- launcher ----------------
extern "C" void kernel_launch(void* const* d_in, const int* in_sizes, int n_in,
                              void* d_out, int out_size)
{
    (void)in_sizes; (void)n_in; (void)out_size;
    const float* x    = (const float*)d_in[0];
    const float* ln1s = (const float*)d_in[1];
    const float* ln1b = (const float*)d_in[2];
    const float* ln2s = (const float*)d_in[3];
    const float* ln2b = (const float*)d_in[4];
    const float* Wq   = (const float*)d_in[5];
    const float* bq   = (const float*)d_in[6];
    const float* Wk   = (const float*)d_in[7];
    const float* bk   = (const float*)d_in[8];
    const float* Wv   = (const float*)d_in[9];
    const float* bv   = (const float*)d_in[10];
    const float* Wo   = (const float*)d_in[11];
    const float* bo   = (const float*)d_in[12];
    const float* W1   = (const float*)d_in[13];
    const float* b1   = (const float*)d_in[14];
    const float* W2   = (const float*)d_in[15];
    const float* b2   = (const float*)d_in[16];
    float* out = (float*)d_out;

    float *y, *q, *k, *v, *o, *x1, *ffn, *sc;
    cudaGetSymbolAddress((void**)&y,   g_y);
    cudaGetSymbolAddress((void**)&q,   g_q);
    cudaGetSymbolAddress((void**)&k,   g_k);
    cudaGetSymbolAddress((void**)&v,   g_v);
    cudaGetSymbolAddress((void**)&o,   g_o);
    cudaGetSymbolAddress((void**)&x1,  g_x1);
    cudaGetSymbolAddress((void**)&ffn, g_ffn);
    cudaGetSymbolAddress((void**)&sc,  g_scores);

    const long long headStride = (long long)S_LEN * S_LEN;

    // 1) LN1
    ln_kernel<<<S_LEN, 256>>>(x, ln1s, ln1b, y);

    // 2) QKV projections (+bias)
    dim3 gqkv(D_DIM / 64, S_LEN / 64);
    gemm64<false><<<gqkv, 256>>>(y, D_DIM, 0, Wq, D_DIM, 0, q, D_DIM, 0,
                                 D_DIM, bq, nullptr, EPI_BIAS);
    gemm64<false><<<gqkv, 256>>>(y, D_DIM, 0, Wk, D_DIM, 0, k, D_DIM, 0,
                                 D_DIM, bk, nullptr, EPI_BIAS);
    gemm64<false><<<gqkv, 256>>>(y, D_DIM, 0, Wv, D_DIM, 0, v, D_DIM, 0,
                                 D_DIM, bv, nullptr, EPI_BIAS);

    // 3) RoPE on q, k
    rope_kernel<<<dim3(S_LEN, NH), 32>>>(q);
    rope_kernel<<<dim3(S_LEN, NH), 32>>>(k);

    // 4) scores[h] = q_h @ k_h^T   (batched over heads via z; per-head col offset 64)
    dim3 gsc(S_LEN / 64, S_LEN / 64, NH);
    gemm64<true><<<gsc, 256>>>(q, D_DIM, 64, k, D_DIM, 64,
                               sc, S_LEN, headStride,
                               HDIM, nullptr, nullptr, EPI_NONE);

    // 5) softmax over k axis, with 1/sqrt(HD) scale
    softmax_kernel<<<NH * S_LEN, 256>>>(sc, 0.125f);

    // 6) o[h] = p_h @ v_h
    dim3 gpv(HDIM / 64, S_LEN / 64, NH);
    gemm64<false><<<gpv, 256>>>(sc, S_LEN, headStride, v, D_DIM, 64,
                                o, D_DIM, 64,
                                S_LEN, nullptr, nullptr, EPI_NONE);

    // 7) attn_out = o @ Wo + bo + x   -> x1
    dim3 go(D_DIM / 64, S_LEN / 64);
    gemm64<false><<<go, 256>>>(o, D_DIM, 0, Wo, D_DIM, 0, x1, D_DIM, 0,
                               D_DIM, bo, x, EPI_BIAS_RES);

    // 8) LN2
    ln_kernel<<<S_LEN, 256>>>(x1, ln2s, ln2b, y);

    // 9) ffn = gelu(y @ W1 + b1)
    dim3 gf1(FF_D / 64, S_LEN / 64);
    gemm64<false><<<gf1, 256>>>(y, D_DIM, 0, W1, FF_D, 0, ffn, FF_D, 0,
                                D_DIM, b1, nullptr, EPI_BIAS_GELU);

    // 10) out = ffn @ W2 + b2 + x1
    dim3 gf2(D_DIM / 64, S_LEN / 64);
    gemm64<false><<<gf2, 256>>>(ffn, FF_D, 0, W2, D_DIM, 0, out, D_DIM, 0,
                                FF_D, b2, x1, EPI_BIAS_RES);
}

// round 4
// speedup vs baseline: 3.2709x; 3.2709x over previous
#include <cuda_runtime.h>
#include <cstdint>
#include <math.h>

// Problem constants
#define S_LEN 4096
#define D_DIM 1024
#define NH    16
#define HDIM  64
#define FF_D  4096

#define EPI_NONE      0
#define EPI_BIAS      1
#define EPI_BIAS_RES  2
#define EPI_BIAS_GELU 3

// ---------------- scratch (device globals: allocation-free rule) ----------------
__device__ float g_y  [S_LEN * D_DIM];
__device__ float g_q  [S_LEN * D_DIM];
__device__ float g_k  [S_LEN * D_DIM];
__device__ float g_v  [S_LEN * D_DIM];
__device__ float g_o  [S_LEN * D_DIM];
__device__ float g_x1 [S_LEN * D_DIM];
__device__ float g_ffn[S_LEN * FF_D];
__device__ float g_scores[268435456];              // 16 * 4096 * 4096
__device__ float g_WqT[D_DIM * D_DIM];
__device__ float g_WkT[D_DIM * D_DIM];
__device__ float g_WvT[D_DIM * D_DIM];
__device__ float g_WoT[D_DIM * D_DIM];
__device__ float g_W1T[(long long)FF_D * D_DIM];
__device__ float g_W2T[(long long)D_DIM * FF_D];
__device__ float g_vT [(long long)D_DIM * S_LEN];

// ---------------- helpers ----------------
__device__ __forceinline__ uint32_t smem_u32(const void* p) {
    uint32_t a;
    asm("{ .reg .u64 t; cvta.to.shared.u64 t, %1; cvt.u32.u64 %0, t; }" : "=r"(a) : "l"(p));
    return a;
}
__device__ __forceinline__ void cp_async16(uint32_t s, const void* g) {
    asm volatile("cp.async.cg.shared.global [%0], [%1], 16;" :: "r"(s), "l"(g));
}
__device__ __forceinline__ void cp_commit() {
    asm volatile("cp.async.commit_group;" ::: "memory");
}
__device__ __forceinline__ void cp_wait(int n) {
    if (n == 0)      asm volatile("cp.async.wait_group 0;" ::: "memory");
    else if (n == 1) asm volatile("cp.async.wait_group 1;" ::: "memory");
    else             asm volatile("cp.async.wait_group 2;" ::: "memory");
}
__device__ __forceinline__ void mma_tf32(float* c, const uint32_t* a,
                                         uint32_t b0, uint32_t b1) {
    asm volatile(
        "mma.sync.aligned.m16n8k8.row.col.f32.tf32.tf32.f32 "
        "{%0,%1,%2,%3}, {%4,%5,%6,%7}, {%8,%9}, {%0,%1,%2,%3};"
        : "+f"(c[0]), "+f"(c[1]), "+f"(c[2]), "+f"(c[3])
        : "r"(a[0]), "r"(a[1]), "r"(a[2]), "r"(a[3]), "r"(b0), "r"(b1));
}
__device__ __forceinline__ float gelu_exact(float v) {
    return 0.5f * v * (1.0f + erff(v * 0.70710678118654752f));
}

// ---------------- LayerNorm ----------------
__global__ __launch_bounds__(256) void ln_kernel(const float* __restrict__ x,
                                                 const float* __restrict__ sc,
                                                 const float* __restrict__ bi,
                                                 float* __restrict__ y)
{
    long long row = blockIdx.x;
    const float* xr = x + row * D_DIM;
    int c = threadIdx.x << 2;
    float4 xv = *(const float4*)(xr + c);
    float s  = xv.x + xv.y + xv.z + xv.w;
    float ss = xv.x*xv.x + xv.y*xv.y + xv.z*xv.z + xv.w*xv.w;
    #pragma unroll
    for (int off = 16; off; off >>= 1) {
        s  += __shfl_down_sync(0xffffffffu, s,  off);
        ss += __shfl_down_sync(0xffffffffu, ss, off);
    }
    __shared__ float sbuf[8], ssbuf[8];
    __shared__ float mu_s, rinv_s;
    int w = threadIdx.x >> 5, l = threadIdx.x & 31;
    if (l == 0) { sbuf[w] = s; ssbuf[w] = ss; }
    __syncthreads();
    if (threadIdx.x == 0) {
        float S = 0.f, SS = 0.f;
        #pragma unroll
        for (int i = 0; i < 8; i++) { S += sbuf[i]; SS += ssbuf[i]; }
        float mu  = S * (1.0f / D_DIM);
        float var = SS * (1.0f / D_DIM) - mu * mu;
        mu_s = mu;
        rinv_s = rsqrtf(var + 1e-6f);
    }
    __syncthreads();
    float mu = mu_s, rinv = rinv_s;
    float4 scv = *(const float4*)(sc + c);
    float4 bv  = *(const float4*)(bi + c);
    float4 ov;
    ov.x = (xv.x - mu) * rinv * scv.x + bv.x;
    ov.y = (xv.y - mu) * rinv * scv.y + bv.y;
    ov.z = (xv.z - mu) * rinv * scv.z + bv.z;
    ov.w = (xv.w - mu) * rinv * scv.w + bv.w;
    *(float4*)(y + row * D_DIM + c) = ov;
}

// ---------------- RoPE (in place, optional output scale) ----------------
__global__ void rope_kernel(float* __restrict__ buf, float scale)
{
    int c = threadIdx.x;                 // 0..31
    int s = blockIdx.x;
    int h = blockIdx.y;
    float* p = buf + (long long)s * D_DIM + h * HDIM;
    float freq = expf(-(float)c * (9.210340371976184f / 32.0f));
    float ang = (float)s * freq;
    float sn, cs;
    sincosf(ang, &sn, &cs);
    float x1 = p[c], x2 = p[c + 32];
    p[c]      = (x1 * cs - x2 * sn) * scale;
    p[c + 32] = (x2 * cs + x1 * sn) * scale;
}

// ---------------- row softmax over 4096 cols (in place) ----------------
__global__ __launch_bounds__(256) void softmax_kernel(float* __restrict__ scores)
{
    long long row = blockIdx.x;
    float* p = scores + row * S_LEN;
    float vals[16];
    float m = -3.4e38f;
    #pragma unroll
    for (int j = 0; j < 16; j++) {
        float v = p[threadIdx.x + j * 256];
        vals[j] = v;
        m = fmaxf(m, v);
    }
    #pragma unroll
    for (int off = 16; off; off >>= 1) m = fmaxf(m, __shfl_xor_sync(0xffffffffu, m, off));
    __shared__ float redm[8], reds[8];
    int w = threadIdx.x >> 5, l = threadIdx.x & 31;
    if (l == 0) redm[w] = m;
    __syncthreads();
    m = redm[0];
    #pragma unroll
    for (int i = 1; i < 8; i++) m = fmaxf(m, redm[i]);

    float sum = 0.f;
    #pragma unroll
    for (int j = 0; j < 16; j++) {
        float e = expf(vals[j] - m);
        vals[j] = e;
        sum += e;
    }
    #pragma unroll
    for (int off = 16; off; off >>= 1) sum += __shfl_xor_sync(0xffffffffu, sum, off);
    if (l == 0) reds[w] = sum;
    __syncthreads();
    sum = 0.f;
    #pragma unroll
    for (int i = 0; i < 8; i++) sum += reds[i];
    float rs = 1.0f / sum;
    #pragma unroll
    for (int j = 0; j < 16; j++) p[threadIdx.x + j * 256] = vals[j] * rs;
}

// ---------------- transpose [R,C] -> [C,R] (R, C multiples of 32) ----------------
__global__ void transpose_kernel(const float* __restrict__ in, float* __restrict__ out,
                                 int R, int C)
{
    __shared__ float t[32][33];
    int c0 = blockIdx.x * 32, r0 = blockIdx.y * 32;
    #pragma unroll
    for (int i = 0; i < 32; i += 8)
        t[threadIdx.y + i][threadIdx.x] =
            in[(long long)(r0 + threadIdx.y + i) * C + c0 + threadIdx.x];
    __syncthreads();
    #pragma unroll
    for (int i = 0; i < 32; i += 8)
        out[(long long)(c0 + threadIdx.y + i) * R + r0 + threadIdx.x] =
            t[threadIdx.x][threadIdx.y + i];
}

// ---------------- tf32 mma.sync GEMM ----------------
// C[M,NT-tile] = A[M,K] * B[N,K]^T, fp32 data (read as tf32), fp32 accumulate.
// CTA tile 128 x NT, 256 threads (8 warps), warp tile 32 x NT/2.
// 3-stage cp.async pipeline, K chunk = 32.
template<int NT>
__global__ __launch_bounds__(256, 2) void gemm_mma(
    const float* __restrict__ A, int lda, long long strA,
    const float* __restrict__ B, int ldb, long long strB,
    float* __restrict__ C, int ldc, long long strC,
    int K,
    const float* __restrict__ bias,
    const float* __restrict__ resid,
    int epi)
{
    constexpr int ST  = 3;
    constexpr int PAD = 36;                 // floats per row (32 + 4 pad)
    constexpr int ASZ = 128 * PAD;
    constexpr int BSZ = NT * PAD;
    constexpr int STF = ASZ + BSZ;          // floats per stage
    constexpr int WNC = NT / 2;             // warp n-cols
    constexpr int NTL = WNC / 8;            // n8 tiles per warp

    extern __shared__ float sm[];
    const int tid  = threadIdx.x;
    const int wid  = tid >> 5, lane = tid & 31;
    const int gid  = lane >> 2, tig = lane & 3;
    const int wm   = wid & 3,  wn  = wid >> 2;

    A += strA * blockIdx.z + (long long)(blockIdx.y * 128) * lda;
    B += strB * blockIdx.z + (long long)(blockIdx.x * NT) * ldb;
    C += strC * blockIdx.z;

    const int nch = K >> 5;

    auto load_chunk = [&](int c) {
        float* s = sm + (c % ST) * STF;
        const long long k0 = (long long)c << 5;
        uint32_t sA = smem_u32(s);
        #pragma unroll
        for (int i = 0; i < 4; i++) {                   // A: 128 rows x 8 float4
            int v = tid + (i << 8);
            int r = v >> 3, kq = v & 7;
            cp_async16(sA + (uint32_t)(r * PAD + (kq << 2)) * 4,
                       A + (long long)r * lda + k0 + (kq << 2));
        }
        uint32_t sB = smem_u32(s + ASZ);
        #pragma unroll
        for (int i = 0; i < NT / 32; i++) {             // B: NT rows x 8 float4
            int v = tid + (i << 8);
            int r = v >> 3, kq = v & 7;
            cp_async16(sB + (uint32_t)(r * PAD + (kq << 2)) * 4,
                       B + (long long)r * ldb + k0 + (kq << 2));
        }
        cp_commit();
    };

    float acc[2][NTL][4];
    #pragma unroll
    for (int mt = 0; mt < 2; mt++)
        #pragma unroll
        for (int nt = 0; nt < NTL; nt++)
            #pragma unroll
            for (int j = 0; j < 4; j++) acc[mt][nt][j] = 0.f;

    const int npro = (nch < ST - 1) ? nch : ST - 1;
    for (int s = 0; s < npro; s++) load_chunk(s);

    for (int c = 0; c < nch; c++) {
        int pend = nch - 1 - c;
        if (pend > ST - 2) pend = ST - 2;
        cp_wait(pend);
        __syncthreads();                 // all warps done with buffer (c-1)%ST
        int ln = c + ST - 1;
        if (ln < nch) load_chunk(ln);    // writes buffer (c-1)%ST — safe now

        const float* as = sm + (c % ST) * STF;
        const float* bs = as + ASZ;
        #pragma unroll
        for (int ks = 0; ks < 4; ks++) {
            const int kc = (ks << 3) + tig;
            uint32_t a[2][4];
            #pragma unroll
            for (int mt = 0; mt < 2; mt++) {
                int ar = (wm << 5) + (mt << 4) + gid;
                a[mt][0] = __float_as_uint(as[ar * PAD + kc]);
                a[mt][1] = __float_as_uint(as[(ar + 8) * PAD + kc]);
                a[mt][2] = __float_as_uint(as[ar * PAD + kc + 4]);
                a[mt][3] = __float_as_uint(as[(ar + 8) * PAD + kc + 4]);
            }
            #pragma unroll
            for (int nt = 0; nt < NTL; nt++) {
                int br = wn * WNC + (nt << 3) + gid;
                uint32_t b0 = __float_as_uint(bs[br * PAD + kc]);
                uint32_t b1 = __float_as_uint(bs[br * PAD + kc + 4]);
                mma_tf32(acc[0][nt], a[0], b0, b1);
                mma_tf32(acc[1][nt], a[1], b0, b1);
            }
        }
    }

    // ---------------- epilogue (accums in regs) ----------------
    const int n0 = blockIdx.x * NT + wn * WNC;
    const int m0 = blockIdx.y * 128 + (wm << 5);
    #pragma unroll
    for (int mt = 0; mt < 2; mt++) {
        #pragma unroll
        for (int half = 0; half < 2; half++) {
            const int row = m0 + (mt << 4) + gid + (half << 3);
            float*       Crow = C + (long long)row * ldc;
            const float* Rrow = resid ? (resid + (long long)row * ldc) : nullptr;
            #pragma unroll
            for (int nt = 0; nt < NTL; nt++) {
                const int col = n0 + (nt << 3) + (tig << 1);
                float v0 = acc[mt][nt][(half << 1) + 0];
                float v1 = acc[mt][nt][(half << 1) + 1];
                if (epi != EPI_NONE) { v0 += bias[col]; v1 += bias[col + 1]; }
                if (epi == EPI_BIAS_RES) {
                    float2 rr = *(const float2*)(Rrow + col);
                    v0 += rr.x; v1 += rr.y;
                } else if (epi == EPI_BIAS_GELU) {
                    v0 = gelu_exact(v0); v1 = gelu_exact(v1);
                }
                *(float2*)(Crow + col) = make_float2(v0, v1);
            }
        }
    }
}

// ---------------- launcher ----------------
extern "C" void kernel_launch(void* const* d_in, const int* in_sizes, int n_in,
                              void* d_out, int out_size)
{
    (void)in_sizes; (void)n_in; (void)out_size;
    const float* x    = (const float*)d_in[0];
    const float* ln1s = (const float*)d_in[1];
    const float* ln1b = (const float*)d_in[2];
    const float* ln2s = (const float*)d_in[3];
    const float* ln2b = (const float*)d_in[4];
    const float* Wq   = (const float*)d_in[5];
    const float* bq   = (const float*)d_in[6];
    const float* Wk   = (const float*)d_in[7];
    const float* bk   = (const float*)d_in[8];
    const float* Wv   = (const float*)d_in[9];
    const float* bv   = (const float*)d_in[10];
    const float* Wo   = (const float*)d_in[11];
    const float* bo   = (const float*)d_in[12];
    const float* W1   = (const float*)d_in[13];
    const float* b1   = (const float*)d_in[14];
    const float* W2   = (const float*)d_in[15];
    const float* b2   = (const float*)d_in[16];
    float* out = (float*)d_out;

    float *y, *q, *k, *v, *o, *x1, *ffn, *sc;
    float *WqT, *WkT, *WvT, *WoT, *W1T, *W2T, *vT;
    cudaGetSymbolAddress((void**)&y,   g_y);
    cudaGetSymbolAddress((void**)&q,   g_q);
    cudaGetSymbolAddress((void**)&k,   g_k);
    cudaGetSymbolAddress((void**)&v,   g_v);
    cudaGetSymbolAddress((void**)&o,   g_o);
    cudaGetSymbolAddress((void**)&x1,  g_x1);
    cudaGetSymbolAddress((void**)&ffn, g_ffn);
    cudaGetSymbolAddress((void**)&sc,  g_scores);
    cudaGetSymbolAddress((void**)&WqT, g_WqT);
    cudaGetSymbolAddress((void**)&WkT, g_WkT);
    cudaGetSymbolAddress((void**)&WvT, g_WvT);
    cudaGetSymbolAddress((void**)&WoT, g_WoT);
    cudaGetSymbolAddress((void**)&W1T, g_W1T);
    cudaGetSymbolAddress((void**)&W2T, g_W2T);
    cudaGetSymbolAddress((void**)&vT,  g_vT);

    const int SMEM128 = 3 * (128 + 128) * 36 * 4;   // 110592
    const int SMEM64  = 3 * (128 + 64) * 36 * 4;    // 82944
    cudaFuncSetAttribute(gemm_mma<128>, cudaFuncAttributeMaxDynamicSharedMemorySize, SMEM128);
    cudaFuncSetAttribute(gemm_mma<64>,  cudaFuncAttributeMaxDynamicSharedMemorySize, SMEM64);

    const long long headStride = (long long)S_LEN * S_LEN;
    dim3 tb(32, 8);

    // weight transposes ([K,N] -> [N,K])
    transpose_kernel<<<dim3(32, 32),  tb>>>(Wq, WqT, D_DIM, D_DIM);
    transpose_kernel<<<dim3(32, 32),  tb>>>(Wk, WkT, D_DIM, D_DIM);
    transpose_kernel<<<dim3(32, 32),  tb>>>(Wv, WvT, D_DIM, D_DIM);
    transpose_kernel<<<dim3(32, 32),  tb>>>(Wo, WoT, D_DIM, D_DIM);
    transpose_kernel<<<dim3(128, 32), tb>>>(W1, W1T, D_DIM, FF_D);
    transpose_kernel<<<dim3(32, 128), tb>>>(W2, W2T, FF_D, D_DIM);

    // 1) LN1
    ln_kernel<<<S_LEN, 256>>>(x, ln1s, ln1b, y);

    // 2) QKV projections
    dim3 gqkv(D_DIM / 128, S_LEN / 128);
    gemm_mma<128><<<gqkv, 256, SMEM128>>>(y, D_DIM, 0, WqT, D_DIM, 0, q, D_DIM, 0,
                                          D_DIM, bq, nullptr, EPI_BIAS);
    gemm_mma<128><<<gqkv, 256, SMEM128>>>(y, D_DIM, 0, WkT, D_DIM, 0, k, D_DIM, 0,
                                          D_DIM, bk, nullptr, EPI_BIAS);
    gemm_mma<128><<<gqkv, 256, SMEM128>>>(y, D_DIM, 0, WvT, D_DIM, 0, v, D_DIM, 0,
                                          D_DIM, bv, nullptr, EPI_BIAS);

    // 3) RoPE (1/sqrt(HD) folded into q)
    rope_kernel<<<dim3(S_LEN, NH), 32>>>(q, 0.125f);
    rope_kernel<<<dim3(S_LEN, NH), 32>>>(k, 1.0f);

    // 4) scores[h] = q_h @ k_h^T
    dim3 gsc(S_LEN / 128, S_LEN / 128, NH);
    gemm_mma<128><<<gsc, 256, SMEM128>>>(q, D_DIM, HDIM, k, D_DIM, HDIM,
                                         sc, S_LEN, headStride,
                                         HDIM, nullptr, nullptr, EPI_NONE);

    // 5) softmax
    softmax_kernel<<<NH * S_LEN, 256>>>(sc);

    // 6) vT = v^T ; o[h] = p_h @ v_h
    transpose_kernel<<<dim3(32, 128), tb>>>(v, vT, S_LEN, D_DIM);
    dim3 gpv(1, S_LEN / 128, NH);
    gemm_mma<64><<<gpv, 256, SMEM64>>>(sc, S_LEN, headStride,
                                       vT, S_LEN, (long long)HDIM * S_LEN,
                                       o, D_DIM, HDIM,
                                       S_LEN, nullptr, nullptr, EPI_NONE);

    // 7) x1 = o @ Wo + bo + x
    dim3 go(D_DIM / 128, S_LEN / 128);
    gemm_mma<128><<<go, 256, SMEM128>>>(o, D_DIM, 0, WoT, D_DIM, 0, x1, D_DIM, 0,
                                        D_DIM, bo, x, EPI_BIAS_RES);

    // 8) LN2
    ln_kernel<<<S_LEN, 256>>>(x1, ln2s, ln2b, y);

    // 9) ffn = gelu(y @ W1 + b1)
    dim3 gf1(FF_D / 128, S_LEN / 128);
    gemm_mma<128><<<gf1, 256, SMEM128>>>(y, D_DIM, 0, W1T, D_DIM, 0, ffn, FF_D, 0,
                                         D_DIM, b1, nullptr, EPI_BIAS_GELU);

    // 10) out = ffn @ W2 + b2 + x1
    dim3 gf2(D_DIM / 128, S_LEN / 128);
    gemm_mma<128><<<gf2, 256, SMEM128>>>(ffn, FF_D, 0, W2T, FF_D, 0, out, D_DIM, 0,
                                         FF_D, b2, x1, EPI_BIAS_RES);
}

// round 7
// speedup vs baseline: 4.2115x; 1.2876x over previous
#include <cuda_runtime.h>
#include <cstdint>
#include <math.h>

// Problem constants
#define S_LEN 4096
#define D_DIM 1024
#define NH    16
#define HDIM  64
#define FF_D  4096
#define KT    64

#define EPI_NONE      0
#define EPI_BIAS      1
#define EPI_BIAS_RES  2
#define EPI_BIAS_GELU 3

// ---------------- scratch (device globals: allocation-free rule) ----------------
__device__ float g_y  [S_LEN * D_DIM];
__device__ float g_q  [S_LEN * D_DIM];
__device__ float g_k  [S_LEN * D_DIM];
__device__ float g_v  [S_LEN * D_DIM];
__device__ float g_o  [S_LEN * D_DIM];
__device__ float g_x1 [S_LEN * D_DIM];
__device__ float g_ffn[S_LEN * FF_D];
__device__ float g_WqT[D_DIM * D_DIM];
__device__ float g_WkT[D_DIM * D_DIM];
__device__ float g_WvT[D_DIM * D_DIM];
__device__ float g_WoT[D_DIM * D_DIM];
__device__ float g_W1T[(long long)FF_D * D_DIM];
__device__ float g_W2T[(long long)D_DIM * FF_D];
__device__ float g_vT [(long long)D_DIM * S_LEN];

// ---------------- helpers ----------------
__device__ __forceinline__ uint32_t smem_u32(const void* p) {
    uint32_t a;
    asm("{ .reg .u64 t; cvta.to.shared.u64 t, %1; cvt.u32.u64 %0, t; }" : "=r"(a) : "l"(p));
    return a;
}
__device__ __forceinline__ void cp_async16(uint32_t s, const void* g) {
    asm volatile("cp.async.cg.shared.global [%0], [%1], 16;" :: "r"(s), "l"(g));
}
__device__ __forceinline__ void cp_commit() {
    asm volatile("cp.async.commit_group;" ::: "memory");
}
__device__ __forceinline__ void cp_wait(int n) {
    if (n == 0)      asm volatile("cp.async.wait_group 0;" ::: "memory");
    else if (n == 1) asm volatile("cp.async.wait_group 1;" ::: "memory");
    else             asm volatile("cp.async.wait_group 2;" ::: "memory");
}
__device__ __forceinline__ void mma_tf32(float* c, const uint32_t* a,
                                         uint32_t b0, uint32_t b1) {
    asm volatile(
        "mma.sync.aligned.m16n8k8.row.col.f32.tf32.tf32.f32 "
        "{%0,%1,%2,%3}, {%4,%5,%6,%7}, {%8,%9}, {%0,%1,%2,%3};"
        : "+f"(c[0]), "+f"(c[1]), "+f"(c[2]), "+f"(c[3])
        : "r"(a[0]), "r"(a[1]), "r"(a[2]), "r"(a[3]), "r"(b0), "r"(b1));
}
__device__ __forceinline__ float gelu_exact(float v) {
    return 0.5f * v * (1.0f + erff(v * 0.70710678118654752f));
}

// ---------------- LayerNorm ----------------
__global__ __launch_bounds__(256) void ln_kernel(const float* __restrict__ x,
                                                 const float* __restrict__ sc,
                                                 const float* __restrict__ bi,
                                                 float* __restrict__ y)
{
    long long row = blockIdx.x;
    const float* xr = x + row * D_DIM;
    int c = threadIdx.x << 2;
    float4 xv = *(const float4*)(xr + c);
    float s  = xv.x + xv.y + xv.z + xv.w;
    float ss = xv.x*xv.x + xv.y*xv.y + xv.z*xv.z + xv.w*xv.w;
    #pragma unroll
    for (int off = 16; off; off >>= 1) {
        s  += __shfl_down_sync(0xffffffffu, s,  off);
        ss += __shfl_down_sync(0xffffffffu, ss, off);
    }
    __shared__ float sbuf[8], ssbuf[8];
    __shared__ float mu_s, rinv_s;
    int w = threadIdx.x >> 5, l = threadIdx.x & 31;
    if (l == 0) { sbuf[w] = s; ssbuf[w] = ss; }
    __syncthreads();
    if (threadIdx.x == 0) {
        float S = 0.f, SS = 0.f;
        #pragma unroll
        for (int i = 0; i < 8; i++) { S += sbuf[i]; SS += ssbuf[i]; }
        float mu  = S * (1.0f / D_DIM);
        float var = SS * (1.0f / D_DIM) - mu * mu;
        mu_s = mu;
        rinv_s = rsqrtf(var + 1e-6f);
    }
    __syncthreads();
    float mu = mu_s, rinv = rinv_s;
    float4 scv = *(const float4*)(sc + c);
    float4 bv  = *(const float4*)(bi + c);
    float4 ov;
    ov.x = (xv.x - mu) * rinv * scv.x + bv.x;
    ov.y = (xv.y - mu) * rinv * scv.y + bv.y;
    ov.z = (xv.z - mu) * rinv * scv.z + bv.z;
    ov.w = (xv.w - mu) * rinv * scv.w + bv.w;
    *(float4*)(y + row * D_DIM + c) = ov;
}

// ---------------- RoPE (in place, optional output scale) ----------------
__global__ void rope_kernel(float* __restrict__ buf, float scale)
{
    int c = threadIdx.x;                 // 0..31
    int s = blockIdx.x;
    int h = blockIdx.y;
    float* p = buf + (long long)s * D_DIM + h * HDIM;
    float freq = expf(-(float)c * (9.210340371976184f / 32.0f));
    float ang = (float)s * freq;
    float sn, cs;
    sincosf(ang, &sn, &cs);
    float x1 = p[c], x2 = p[c + 32];
    p[c]      = (x1 * cs - x2 * sn) * scale;
    p[c + 32] = (x2 * cs + x1 * sn) * scale;
}

// ---------------- transpose [R,C] -> [C,R] (R, C multiples of 32) ----------------
__global__ void transpose_kernel(const float* __restrict__ in, float* __restrict__ out,
                                 int R, int C)
{
    __shared__ float t[32][33];
    int c0 = blockIdx.x * 32, r0 = blockIdx.y * 32;
    #pragma unroll
    for (int i = 0; i < 32; i += 8)
        t[threadIdx.y + i][threadIdx.x] =
            in[(long long)(r0 + threadIdx.y + i) * C + c0 + threadIdx.x];
    __syncthreads();
    #pragma unroll
    for (int i = 0; i < 32; i += 8)
        out[(long long)(c0 + threadIdx.y + i) * R + r0 + threadIdx.x] =
            t[threadIdx.x][threadIdx.y + i];
}

// ---------------- fused flash attention ----------------
// One CTA = (128 q-rows, one head). 8 warps, each owns 16 q-rows x full tile.
// K/V tiles of 64 keys, double-buffered cp.async. Online softmax, O in regs.
// q pre-scaled by 1/sqrt(HD); vt is V^T laid out [h*HD+d][s].
__global__ __launch_bounds__(256, 2) void flash_kernel(
    const float* __restrict__ q, const float* __restrict__ k,
    const float* __restrict__ vt, float* __restrict__ o)
{
    constexpr int PADR = 68;                 // floats per smem row (64 + 4)
    constexpr int TSZ  = 64 * PADR;
    extern __shared__ float sm[];
    float* Ks = sm;                          // [2][64][PADR]
    float* Vs = sm + 2 * TSZ;                // [2][64][PADR]
    float* Ps = sm + 4 * TSZ;                // [128][PADR] (Q staging, then P)

    const int tid  = threadIdx.x;
    const int wid  = tid >> 5, lane = tid & 31;
    const int gid  = lane >> 2, tig = lane & 3;
    const int h    = blockIdx.y;
    const int m0   = blockIdx.x * 128;

    // ---- stage Q tile, extract per-warp fragments into registers ----
    {
        uint32_t sQ = smem_u32(Ps);
        #pragma unroll
        for (int i = 0; i < 8; i++) {        // 128 rows x 16 float4
            int t = tid + (i << 8);
            int r = t >> 4, dq = t & 15;
            cp_async16(sQ + (uint32_t)(r * PADR + (dq << 2)) * 4,
                       q + (long long)(m0 + r) * D_DIM + h * HDIM + (dq << 2));
        }
        cp_commit();
    }
    cp_wait(0);
    __syncthreads();

    uint32_t qf[8][4];
    {
        const float* Qw = Ps + (wid * 16) * PADR;
        #pragma unroll
        for (int ks = 0; ks < 8; ks++) {
            int kc = (ks << 3) + tig;
            qf[ks][0] = __float_as_uint(Qw[gid * PADR + kc]);
            qf[ks][1] = __float_as_uint(Qw[(gid + 8) * PADR + kc]);
            qf[ks][2] = __float_as_uint(Qw[gid * PADR + kc + 4]);
            qf[ks][3] = __float_as_uint(Qw[(gid + 8) * PADR + kc + 4]);
        }
    }
    __syncthreads();                         // Ps now reusable for P

    float oacc[8][4] = {};
    float m0r = -1e30f, m1r = -1e30f;
    float l0r = 0.f,    l1r = 0.f;

    auto load_tile = [&](int kt) {
        int st = kt & 1;
        uint32_t sK = smem_u32(Ks + st * TSZ);
        uint32_t sV = smem_u32(Vs + st * TSZ);
        const long long j0 = (long long)kt * KT;
        #pragma unroll
        for (int i = 0; i < 4; i++) {        // K: 64 rows x 16 float4
            int t = tid + (i << 8);
            int r = t >> 4, dq = t & 15;
            cp_async16(sK + (uint32_t)(r * PADR + (dq << 2)) * 4,
                       k + (j0 + r) * D_DIM + h * HDIM + (dq << 2));
        }
        #pragma unroll
        for (int i = 0; i < 4; i++) {        // V^T: rows = d, cols = j
            int t = tid + (i << 8);
            int r = t >> 4, dq = t & 15;
            cp_async16(sV + (uint32_t)(r * PADR + (dq << 2)) * 4,
                       vt + (long long)(h * HDIM + r) * S_LEN + j0 + (dq << 2));
        }
        cp_commit();
    };

    load_tile(0);

    for (int kt = 0; kt < S_LEN / KT; kt++) {
        cp_wait(0);
        __syncthreads();
        if (kt + 1 < S_LEN / KT) load_tile(kt + 1);

        const float* Kt = Ks + (kt & 1) * TSZ;
        const float* Vt = Vs + (kt & 1) * TSZ;

        // ---- S = Q @ K^T (16 x 64 per warp) ----
        float sacc[8][4] = {};
        #pragma unroll
        for (int ks = 0; ks < 8; ks++) {
            int kc = (ks << 3) + tig;
            #pragma unroll
            for (int nt = 0; nt < 8; nt++) {
                int br = (nt << 3) + gid;
                uint32_t b0 = __float_as_uint(Kt[br * PADR + kc]);
                uint32_t b1 = __float_as_uint(Kt[br * PADR + kc + 4]);
                mma_tf32(sacc[nt], qf[ks], b0, b1);
            }
        }

        // ---- online softmax ----
        float mx0 = -1e30f, mx1 = -1e30f;
        #pragma unroll
        for (int nt = 0; nt < 8; nt++) {
            mx0 = fmaxf(mx0, fmaxf(sacc[nt][0], sacc[nt][1]));
            mx1 = fmaxf(mx1, fmaxf(sacc[nt][2], sacc[nt][3]));
        }
        mx0 = fmaxf(mx0, __shfl_xor_sync(0xffffffffu, mx0, 1));
        mx0 = fmaxf(mx0, __shfl_xor_sync(0xffffffffu, mx0, 2));
        mx1 = fmaxf(mx1, __shfl_xor_sync(0xffffffffu, mx1, 1));
        mx1 = fmaxf(mx1, __shfl_xor_sync(0xffffffffu, mx1, 2));
        float mn0 = fmaxf(m0r, mx0), mn1 = fmaxf(m1r, mx1);
        float sc0 = __expf(m0r - mn0), sc1 = __expf(m1r - mn1);
        m0r = mn0; m1r = mn1;

        float rs0 = 0.f, rs1 = 0.f;
        #pragma unroll
        for (int nt = 0; nt < 8; nt++) {
            sacc[nt][0] = __expf(sacc[nt][0] - mn0);
            sacc[nt][1] = __expf(sacc[nt][1] - mn0);
            sacc[nt][2] = __expf(sacc[nt][2] - mn1);
            sacc[nt][3] = __expf(sacc[nt][3] - mn1);
            rs0 += sacc[nt][0] + sacc[nt][1];
            rs1 += sacc[nt][2] + sacc[nt][3];
        }
        rs0 += __shfl_xor_sync(0xffffffffu, rs0, 1);
        rs0 += __shfl_xor_sync(0xffffffffu, rs0, 2);
        rs1 += __shfl_xor_sync(0xffffffffu, rs1, 1);
        rs1 += __shfl_xor_sync(0xffffffffu, rs1, 2);
        l0r = l0r * sc0 + rs0;
        l1r = l1r * sc1 + rs1;

        #pragma unroll
        for (int nt = 0; nt < 8; nt++) {
            oacc[nt][0] *= sc0; oacc[nt][1] *= sc0;
            oacc[nt][2] *= sc1; oacc[nt][3] *= sc1;
        }

        // ---- P -> smem (per-warp rows), refragment, O += P @ V ----
        float* Pw = Ps + (wid * 16) * PADR;
        #pragma unroll
        for (int nt = 0; nt < 8; nt++) {
            int c = (nt << 3) + (tig << 1);
            *(float2*)&Pw[gid * PADR + c]       = make_float2(sacc[nt][0], sacc[nt][1]);
            *(float2*)&Pw[(gid + 8) * PADR + c] = make_float2(sacc[nt][2], sacc[nt][3]);
        }
        __syncwarp();
        #pragma unroll
        for (int ks = 0; ks < 8; ks++) {
            int kc = (ks << 3) + tig;
            uint32_t a[4];
            a[0] = __float_as_uint(Pw[gid * PADR + kc]);
            a[1] = __float_as_uint(Pw[(gid + 8) * PADR + kc]);
            a[2] = __float_as_uint(Pw[gid * PADR + kc + 4]);
            a[3] = __float_as_uint(Pw[(gid + 8) * PADR + kc + 4]);
            #pragma unroll
            for (int nt = 0; nt < 8; nt++) {
                int br = (nt << 3) + gid;
                uint32_t b0 = __float_as_uint(Vt[br * PADR + kc]);
                uint32_t b1 = __float_as_uint(Vt[br * PADR + kc + 4]);
                mma_tf32(oacc[nt], a, b0, b1);
            }
        }
    }

    // ---- epilogue: normalize, write ----
    float rl0 = 1.f / l0r, rl1 = 1.f / l1r;
    const int r0 = m0 + wid * 16 + gid;
    #pragma unroll
    for (int nt = 0; nt < 8; nt++) {
        int c = h * HDIM + (nt << 3) + (tig << 1);
        *(float2*)&o[(long long)r0 * D_DIM + c] =
            make_float2(oacc[nt][0] * rl0, oacc[nt][1] * rl0);
        *(float2*)&o[(long long)(r0 + 8) * D_DIM + c] =
            make_float2(oacc[nt][2] * rl1, oacc[nt][3] * rl1);
    }
}

// ---------------- tf32 mma.sync GEMM (dense projections / FFN) ----------------
template<int NT>
__global__ __launch_bounds__(256, 2) void gemm_mma(
    const float* __restrict__ A, int lda, long long strA,
    const float* __restrict__ B, int ldb, long long strB,
    float* __restrict__ C, int ldc, long long strC,
    int K,
    const float* __restrict__ bias,
    const float* __restrict__ resid,
    int epi)
{
    constexpr int ST  = 3;
    constexpr int PAD = 36;
    constexpr int ASZ = 128 * PAD;
    constexpr int BSZ = NT * PAD;
    constexpr int STF = ASZ + BSZ;
    constexpr int WNC = NT / 2;
    constexpr int NTL = WNC / 8;

    extern __shared__ float sm[];
    const int tid  = threadIdx.x;
    const int wid  = tid >> 5, lane = tid & 31;
    const int gid  = lane >> 2, tig = lane & 3;
    const int wm   = wid & 3,  wn  = wid >> 2;

    A += strA * blockIdx.z + (long long)(blockIdx.y * 128) * lda;
    B += strB * blockIdx.z + (long long)(blockIdx.x * NT) * ldb;
    C += strC * blockIdx.z;

    const int nch = K >> 5;

    auto load_chunk = [&](int c) {
        float* s = sm + (c % ST) * STF;
        const long long k0 = (long long)c << 5;
        uint32_t sA = smem_u32(s);
        #pragma unroll
        for (int i = 0; i < 4; i++) {
            int v = tid + (i << 8);
            int r = v >> 3, kq = v & 7;
            cp_async16(sA + (uint32_t)(r * PAD + (kq << 2)) * 4,
                       A + (long long)r * lda + k0 + (kq << 2));
        }
        uint32_t sB = smem_u32(s + ASZ);
        #pragma unroll
        for (int i = 0; i < NT / 32; i++) {
            int v = tid + (i << 8);
            int r = v >> 3, kq = v & 7;
            cp_async16(sB + (uint32_t)(r * PAD + (kq << 2)) * 4,
                       B + (long long)r * ldb + k0 + (kq << 2));
        }
        cp_commit();
    };

    float acc[2][NTL][4];
    #pragma unroll
    for (int mt = 0; mt < 2; mt++)
        #pragma unroll
        for (int nt = 0; nt < NTL; nt++)
            #pragma unroll
            for (int j = 0; j < 4; j++) acc[mt][nt][j] = 0.f;

    const int npro = (nch < ST - 1) ? nch : ST - 1;
    for (int s = 0; s < npro; s++) load_chunk(s);

    for (int c = 0; c < nch; c++) {
        int pend = nch - 1 - c;
        if (pend > ST - 2) pend = ST - 2;
        cp_wait(pend);
        __syncthreads();
        int ln = c + ST - 1;
        if (ln < nch) load_chunk(ln);

        const float* as = sm + (c % ST) * STF;
        const float* bs = as + ASZ;
        #pragma unroll
        for (int ks = 0; ks < 4; ks++) {
            const int kc = (ks << 3) + tig;
            uint32_t a[2][4];
            #pragma unroll
            for (int mt = 0; mt < 2; mt++) {
                int ar = (wm << 5) + (mt << 4) + gid;
                a[mt][0] = __float_as_uint(as[ar * PAD + kc]);
                a[mt][1] = __float_as_uint(as[(ar + 8) * PAD + kc]);
                a[mt][2] = __float_as_uint(as[ar * PAD + kc + 4]);
                a[mt][3] = __float_as_uint(as[(ar + 8) * PAD + kc + 4]);
            }
            #pragma unroll
            for (int nt = 0; nt < NTL; nt++) {
                int br = wn * WNC + (nt << 3) + gid;
                uint32_t b0 = __float_as_uint(bs[br * PAD + kc]);
                uint32_t b1 = __float_as_uint(bs[br * PAD + kc + 4]);
                mma_tf32(acc[0][nt], a[0], b0, b1);
                mma_tf32(acc[1][nt], a[1], b0, b1);
            }
        }
    }

    const int n0 = blockIdx.x * NT + wn * WNC;
    const int m0 = blockIdx.y * 128 + (wm << 5);
    #pragma unroll
    for (int mt = 0; mt < 2; mt++) {
        #pragma unroll
        for (int half = 0; half < 2; half++) {
            const int row = m0 + (mt << 4) + gid + (half << 3);
            float*       Crow = C + (long long)row * ldc;
            const float* Rrow = resid ? (resid + (long long)row * ldc) : nullptr;
            #pragma unroll
            for (int nt = 0; nt < NTL; nt++) {
                const int col = n0 + (nt << 3) + (tig << 1);
                float v0 = acc[mt][nt][(half << 1) + 0];
                float v1 = acc[mt][nt][(half << 1) + 1];
                if (epi != EPI_NONE) { v0 += bias[col]; v1 += bias[col + 1]; }
                if (epi == EPI_BIAS_RES) {
                    float2 rr = *(const float2*)(Rrow + col);
                    v0 += rr.x; v1 += rr.y;
                } else if (epi == EPI_BIAS_GELU) {
                    v0 = gelu_exact(v0); v1 = gelu_exact(v1);
                }
                *(float2*)(Crow + col) = make_float2(v0, v1);
            }
        }
    }
}

// ---------------- launcher ----------------
extern "C" void kernel_launch(void* const* d_in, const int* in_sizes, int n_in,
                              void* d_out, int out_size)
{
    (void)in_sizes; (void)n_in; (void)out_size;
    const float* x    = (const float*)d_in[0];
    const float* ln1s = (const float*)d_in[1];
    const float* ln1b = (const float*)d_in[2];
    const float* ln2s = (const float*)d_in[3];
    const float* ln2b = (const float*)d_in[4];
    const float* Wq   = (const float*)d_in[5];
    const float* bq   = (const float*)d_in[6];
    const float* Wk   = (const float*)d_in[7];
    const float* bk   = (const float*)d_in[8];
    const float* Wv   = (const float*)d_in[9];
    const float* bv   = (const float*)d_in[10];
    const float* Wo   = (const float*)d_in[11];
    const float* bo   = (const float*)d_in[12];
    const float* W1   = (const float*)d_in[13];
    const float* b1   = (const float*)d_in[14];
    const float* W2   = (const float*)d_in[15];
    const float* b2   = (const float*)d_in[16];
    float* out = (float*)d_out;

    float *y, *q, *k, *v, *o, *x1, *ffn;
    float *WqT, *WkT, *WvT, *WoT, *W1T, *W2T, *vT;
    cudaGetSymbolAddress((void**)&y,   g_y);
    cudaGetSymbolAddress((void**)&q,   g_q);
    cudaGetSymbolAddress((void**)&k,   g_k);
    cudaGetSymbolAddress((void**)&v,   g_v);
    cudaGetSymbolAddress((void**)&o,   g_o);
    cudaGetSymbolAddress((void**)&x1,  g_x1);
    cudaGetSymbolAddress((void**)&ffn, g_ffn);
    cudaGetSymbolAddress((void**)&WqT, g_WqT);
    cudaGetSymbolAddress((void**)&WkT, g_WkT);
    cudaGetSymbolAddress((void**)&WvT, g_WvT);
    cudaGetSymbolAddress((void**)&WoT, g_WoT);
    cudaGetSymbolAddress((void**)&W1T, g_W1T);
    cudaGetSymbolAddress((void**)&W2T, g_W2T);
    cudaGetSymbolAddress((void**)&vT,  g_vT);

    const int SMEM128  = 3 * (128 + 128) * 36 * 4;            // 110592
    const int SMEMFL   = (4 * 64 * 68 + 128 * 68) * 4;        // 104448
    cudaFuncSetAttribute(gemm_mma<128>, cudaFuncAttributeMaxDynamicSharedMemorySize, SMEM128);
    cudaFuncSetAttribute(flash_kernel,  cudaFuncAttributeMaxDynamicSharedMemorySize, SMEMFL);

    dim3 tb(32, 8);

    // weight transposes ([K,N] -> [N,K])
    transpose_kernel<<<dim3(32, 32),  tb>>>(Wq, WqT, D_DIM, D_DIM);
    transpose_kernel<<<dim3(32, 32),  tb>>>(Wk, WkT, D_DIM, D_DIM);
    transpose_kernel<<<dim3(32, 32),  tb>>>(Wv, WvT, D_DIM, D_DIM);
    transpose_kernel<<<dim3(32, 32),  tb>>>(Wo, WoT, D_DIM, D_DIM);
    transpose_kernel<<<dim3(128, 32), tb>>>(W1, W1T, D_DIM, FF_D);
    transpose_kernel<<<dim3(32, 128), tb>>>(W2, W2T, FF_D, D_DIM);

    // 1) LN1
    ln_kernel<<<S_LEN, 256>>>(x, ln1s, ln1b, y);

    // 2) QKV projections
    dim3 gqkv(D_DIM / 128, S_LEN / 128);
    gemm_mma<128><<<gqkv, 256, SMEM128>>>(y, D_DIM, 0, WqT, D_DIM, 0, q, D_DIM, 0,
                                          D_DIM, bq, nullptr, EPI_BIAS);
    gemm_mma<128><<<gqkv, 256, SMEM128>>>(y, D_DIM, 0, WkT, D_DIM, 0, k, D_DIM, 0,
                                          D_DIM, bk, nullptr, EPI_BIAS);
    gemm_mma<128><<<gqkv, 256, SMEM128>>>(y, D_DIM, 0, WvT, D_DIM, 0, v, D_DIM, 0,
                                          D_DIM, bv, nullptr, EPI_BIAS);

    // 3) RoPE (1/sqrt(HD) folded into q)
    rope_kernel<<<dim3(S_LEN, NH), 32>>>(q, 0.125f);
    rope_kernel<<<dim3(S_LEN, NH), 32>>>(k, 1.0f);

    // 4) V^T for flash PV operand
    transpose_kernel<<<dim3(32, 128), tb>>>(v, vT, S_LEN, D_DIM);

    // 5) fused attention: o = softmax(q k^T) v
    flash_kernel<<<dim3(S_LEN / 128, NH), 256, SMEMFL>>>(q, k, vT, o);

    // 6) x1 = o @ Wo + bo + x
    dim3 go(D_DIM / 128, S_LEN / 128);
    gemm_mma<128><<<go, 256, SMEM128>>>(o, D_DIM, 0, WoT, D_DIM, 0, x1, D_DIM, 0,
                                        D_DIM, bo, x, EPI_BIAS_RES);

    // 7) LN2
    ln_kernel<<<S_LEN, 256>>>(x1, ln2s, ln2b, y);

    // 8) ffn = gelu(y @ W1 + b1)
    dim3 gf1(FF_D / 128, S_LEN / 128);
    gemm_mma<128><<<gf1, 256, SMEM128>>>(y, D_DIM, 0, W1T, D_DIM, 0, ffn, FF_D, 0,
                                         D_DIM, b1, nullptr, EPI_BIAS_GELU);

    // 9) out = ffn @ W2 + b2 + x1
    dim3 gf2(D_DIM / 128, S_LEN / 128);
    gemm_mma<128><<<gf2, 256, SMEM128>>>(ffn, FF_D, 0, W2T, FF_D, 0, out, D_DIM, 0,
                                         FF_D, b2, x1, EPI_BIAS_RES);
}

// round 8
// speedup vs baseline: 4.5582x; 1.0823x over previous
#include <cuda_runtime.h>
#include <cstdint>
#include <math.h>

// Problem constants
#define S_LEN 4096
#define D_DIM 1024
#define NH    16
#define HDIM  64
#define FF_D  4096
#define KT    64
#define QKV_N 3072

#define EPI_NONE      0
#define EPI_BIAS      1
#define EPI_BIAS_RES  2
#define EPI_BIAS_GELU 3

// ---------------- scratch (device globals: allocation-free rule) ----------------
__device__ float g_y   [S_LEN * D_DIM];
__device__ float g_qkv [S_LEN * QKV_N];            // [S][3072]: q | k | v
__device__ float g_o   [S_LEN * D_DIM];
__device__ float g_x1  [S_LEN * D_DIM];
__device__ float g_ffn [S_LEN * FF_D];
__device__ float g_Wqkv[(long long)QKV_N * D_DIM]; // [3072][1024] (N,K)
__device__ float g_bqkv[QKV_N];
__device__ float g_WoT [D_DIM * D_DIM];
__device__ float g_W1T [(long long)FF_D * D_DIM];
__device__ float g_W2T [(long long)D_DIM * FF_D];
__device__ float g_vT  [(long long)D_DIM * S_LEN];

// ---------------- helpers ----------------
__device__ __forceinline__ uint32_t smem_u32(const void* p) {
    uint32_t a;
    asm("{ .reg .u64 t; cvta.to.shared.u64 t, %1; cvt.u32.u64 %0, t; }" : "=r"(a) : "l"(p));
    return a;
}
__device__ __forceinline__ void cp_async16(uint32_t s, const void* g) {
    asm volatile("cp.async.cg.shared.global [%0], [%1], 16;" :: "r"(s), "l"(g));
}
__device__ __forceinline__ void cp_commit() {
    asm volatile("cp.async.commit_group;" ::: "memory");
}
__device__ __forceinline__ void cp_wait(int n) {
    if (n == 0)      asm volatile("cp.async.wait_group 0;" ::: "memory");
    else if (n == 1) asm volatile("cp.async.wait_group 1;" ::: "memory");
    else             asm volatile("cp.async.wait_group 2;" ::: "memory");
}
// ldmatrix x4: four 8x8(b16) matrices == four 8x4(tf32) fragments.
__device__ __forceinline__ void ldsm4(uint32_t* r, uint32_t a) {
    asm volatile("ldmatrix.sync.aligned.m8n8.x4.shared.b16 {%0,%1,%2,%3}, [%4];"
        : "=r"(r[0]), "=r"(r[1]), "=r"(r[2]), "=r"(r[3]) : "r"(a));
}
__device__ __forceinline__ void mma_tf32(float* c, const uint32_t* a,
                                         uint32_t b0, uint32_t b1) {
    asm volatile(
        "mma.sync.aligned.m16n8k8.row.col.f32.tf32.tf32.f32 "
        "{%0,%1,%2,%3}, {%4,%5,%6,%7}, {%8,%9}, {%0,%1,%2,%3};"
        : "+f"(c[0]), "+f"(c[1]), "+f"(c[2]), "+f"(c[3])
        : "r"(a[0]), "r"(a[1]), "r"(a[2]), "r"(a[3]), "r"(b0), "r"(b1));
}
__device__ __forceinline__ float gelu_exact(float v) {
    return 0.5f * v * (1.0f + erff(v * 0.70710678118654752f));
}

// ---------------- LayerNorm ----------------
__global__ __launch_bounds__(256) void ln_kernel(const float* __restrict__ x,
                                                 const float* __restrict__ sc,
                                                 const float* __restrict__ bi,
                                                 float* __restrict__ y)
{
    long long row = blockIdx.x;
    const float* xr = x + row * D_DIM;
    int c = threadIdx.x << 2;
    float4 xv = *(const float4*)(xr + c);
    float s  = xv.x + xv.y + xv.z + xv.w;
    float ss = xv.x*xv.x + xv.y*xv.y + xv.z*xv.z + xv.w*xv.w;
    #pragma unroll
    for (int off = 16; off; off >>= 1) {
        s  += __shfl_down_sync(0xffffffffu, s,  off);
        ss += __shfl_down_sync(0xffffffffu, ss, off);
    }
    __shared__ float sbuf[8], ssbuf[8];
    __shared__ float mu_s, rinv_s;
    int w = threadIdx.x >> 5, l = threadIdx.x & 31;
    if (l == 0) { sbuf[w] = s; ssbuf[w] = ss; }
    __syncthreads();
    if (threadIdx.x == 0) {
        float S = 0.f, SS = 0.f;
        #pragma unroll
        for (int i = 0; i < 8; i++) { S += sbuf[i]; SS += ssbuf[i]; }
        float mu  = S * (1.0f / D_DIM);
        float var = SS * (1.0f / D_DIM) - mu * mu;
        mu_s = mu;
        rinv_s = rsqrtf(var + 1e-6f);
    }
    __syncthreads();
    float mu = mu_s, rinv = rinv_s;
    float4 scv = *(const float4*)(sc + c);
    float4 bv  = *(const float4*)(bi + c);
    float4 ov;
    ov.x = (xv.x - mu) * rinv * scv.x + bv.x;
    ov.y = (xv.y - mu) * rinv * scv.y + bv.y;
    ov.z = (xv.z - mu) * rinv * scv.z + bv.z;
    ov.w = (xv.w - mu) * rinv * scv.w + bv.w;
    *(float4*)(y + row * D_DIM + c) = ov;
}

// ---------------- RoPE (in place, row stride ld) ----------------
__global__ void rope_kernel(float* __restrict__ buf, int ld, float scale)
{
    int c = threadIdx.x;                 // 0..31
    int s = blockIdx.x;
    int h = blockIdx.y;
    float* p = buf + (long long)s * ld + h * HDIM;
    float freq = expf(-(float)c * (9.210340371976184f / 32.0f));
    float ang = (float)s * freq;
    float sn, cs;
    sincosf(ang, &sn, &cs);
    float x1 = p[c], x2 = p[c + 32];
    p[c]      = (x1 * cs - x2 * sn) * scale;
    p[c + 32] = (x2 * cs + x1 * sn) * scale;
}

// ---------------- concat 3 bias vectors ----------------
__global__ void concat3_kernel(const float* __restrict__ a, const float* __restrict__ b,
                               const float* __restrict__ c, float* __restrict__ out)
{
    int i = blockIdx.x * 256 + threadIdx.x;
    out[i] = (i < 1024) ? a[i] : ((i < 2048) ? b[i - 1024] : c[i - 2048]);
}

// ---------------- transpose: out[c][r] = in[r][c], strides explicit ----------------
// grid.x covers cols/32, grid.y covers rows/32
__global__ void transpose_kernel(const float* __restrict__ in, int ldin,
                                 float* __restrict__ out, int ldout)
{
    __shared__ float t[32][33];
    int c0 = blockIdx.x * 32, r0 = blockIdx.y * 32;
    #pragma unroll
    for (int i = 0; i < 32; i += 8)
        t[threadIdx.y + i][threadIdx.x] =
            in[(long long)(r0 + threadIdx.y + i) * ldin + c0 + threadIdx.x];
    __syncthreads();
    #pragma unroll
    for (int i = 0; i < 32; i += 8)
        out[(long long)(c0 + threadIdx.y + i) * ldout + r0 + threadIdx.x] =
            t[threadIdx.x][threadIdx.y + i];
}

// ---------------- fused flash attention ----------------
// One CTA = (128 q-rows, one head). 8 warps, each owns 16 q-rows.
// K/V tiles of 64 keys, double-buffered cp.async. Online softmax, O in regs.
// q pre-scaled by 1/sqrt(HD); vt is V^T laid out [h*HD+d][s].
__global__ __launch_bounds__(256, 2) void flash_kernel(
    const float* __restrict__ q, const float* __restrict__ k, int ldqk,
    const float* __restrict__ vt, float* __restrict__ o)
{
    constexpr int PADR = 68;                 // floats per smem row (64 + 4)
    constexpr int TSZ  = 64 * PADR;
    extern __shared__ float sm[];
    float* Ks = sm;                          // [2][64][PADR]
    float* Vs = sm + 2 * TSZ;                // [2][64][PADR]
    float* Ps = sm + 4 * TSZ;                // [128][PADR] (Q staging, then P)

    const int tid  = threadIdx.x;
    const int wid  = tid >> 5, lane = tid & 31;
    const int gid  = lane >> 2, tig = lane & 3;
    const int h    = blockIdx.y;
    const int m0   = blockIdx.x * 128;

    // ldmatrix lane offsets (floats)
    const int aOffF = (wid * 16 + (lane & 15)) * PADR + ((lane >> 4) << 2);
    const int bOffF = (((lane >> 4) << 3) + (lane & 7)) * PADR + (((lane >> 3) & 1) << 2);

    // ---- stage Q tile, extract per-warp fragments via ldmatrix ----
    {
        uint32_t sQ = smem_u32(Ps);
        #pragma unroll
        for (int i = 0; i < 8; i++) {        // 128 rows x 16 float4
            int t = tid + (i << 8);
            int r = t >> 4, dq = t & 15;
            cp_async16(sQ + (uint32_t)(r * PADR + (dq << 2)) * 4,
                       q + (long long)(m0 + r) * ldqk + h * HDIM + (dq << 2));
        }
        cp_commit();
    }
    cp_wait(0);
    __syncthreads();

    uint32_t qf[8][4];
    {
        uint32_t qA = smem_u32(Ps) + aOffF * 4;
        #pragma unroll
        for (int ks = 0; ks < 8; ks++) ldsm4(qf[ks], qA + ks * 32);
    }
    __syncthreads();                         // Ps now reusable for P

    float oacc[8][4] = {};
    float m0r = -1e30f, m1r = -1e30f;
    float l0r = 0.f,    l1r = 0.f;

    auto load_tile = [&](int kt) {
        int st = kt & 1;
        uint32_t sK = smem_u32(Ks + st * TSZ);
        uint32_t sV = smem_u32(Vs + st * TSZ);
        const long long j0 = (long long)kt * KT;
        #pragma unroll
        for (int i = 0; i < 4; i++) {        // K: 64 rows x 16 float4
            int t = tid + (i << 8);
            int r = t >> 4, dq = t & 15;
            cp_async16(sK + (uint32_t)(r * PADR + (dq << 2)) * 4,
                       k + (j0 + r) * ldqk + h * HDIM + (dq << 2));
        }
        #pragma unroll
        for (int i = 0; i < 4; i++) {        // V^T: rows = d, cols = j
            int t = tid + (i << 8);
            int r = t >> 4, dq = t & 15;
            cp_async16(sV + (uint32_t)(r * PADR + (dq << 2)) * 4,
                       vt + (long long)(h * HDIM + r) * S_LEN + j0 + (dq << 2));
        }
        cp_commit();
    };

    load_tile(0);

    for (int kt = 0; kt < S_LEN / KT; kt++) {
        cp_wait(0);
        __syncthreads();
        if (kt + 1 < S_LEN / KT) load_tile(kt + 1);

        const float* Kt = Ks + (kt & 1) * TSZ;
        const float* Vt = Vs + (kt & 1) * TSZ;

        // ---- S = Q @ K^T (16 x 64 per warp) ----
        float sacc[8][4] = {};
        {
            uint32_t kA = smem_u32(Kt) + bOffF * 4;
            #pragma unroll
            for (int ks = 0; ks < 8; ks++) {
                #pragma unroll
                for (int p = 0; p < 4; p++) {
                    uint32_t bb[4];
                    ldsm4(bb, kA + ks * 32 + p * 16 * PADR * 4);
                    mma_tf32(sacc[2 * p],     qf[ks], bb[0], bb[1]);
                    mma_tf32(sacc[2 * p + 1], qf[ks], bb[2], bb[3]);
                }
            }
        }

        // ---- online softmax ----
        float mx0 = -1e30f, mx1 = -1e30f;
        #pragma unroll
        for (int nt = 0; nt < 8; nt++) {
            mx0 = fmaxf(mx0, fmaxf(sacc[nt][0], sacc[nt][1]));
            mx1 = fmaxf(mx1, fmaxf(sacc[nt][2], sacc[nt][3]));
        }
        mx0 = fmaxf(mx0, __shfl_xor_sync(0xffffffffu, mx0, 1));
        mx0 = fmaxf(mx0, __shfl_xor_sync(0xffffffffu, mx0, 2));
        mx1 = fmaxf(mx1, __shfl_xor_sync(0xffffffffu, mx1, 1));
        mx1 = fmaxf(mx1, __shfl_xor_sync(0xffffffffu, mx1, 2));
        float mn0 = fmaxf(m0r, mx0), mn1 = fmaxf(m1r, mx1);
        float sc0 = __expf(m0r - mn0), sc1 = __expf(m1r - mn1);
        m0r = mn0; m1r = mn1;

        float rs0 = 0.f, rs1 = 0.f;
        #pragma unroll
        for (int nt = 0; nt < 8; nt++) {
            sacc[nt][0] = __expf(sacc[nt][0] - mn0);
            sacc[nt][1] = __expf(sacc[nt][1] - mn0);
            sacc[nt][2] = __expf(sacc[nt][2] - mn1);
            sacc[nt][3] = __expf(sacc[nt][3] - mn1);
            rs0 += sacc[nt][0] + sacc[nt][1];
            rs1 += sacc[nt][2] + sacc[nt][3];
        }
        rs0 += __shfl_xor_sync(0xffffffffu, rs0, 1);
        rs0 += __shfl_xor_sync(0xffffffffu, rs0, 2);
        rs1 += __shfl_xor_sync(0xffffffffu, rs1, 1);
        rs1 += __shfl_xor_sync(0xffffffffu, rs1, 2);
        l0r = l0r * sc0 + rs0;
        l1r = l1r * sc1 + rs1;

        #pragma unroll
        for (int nt = 0; nt < 8; nt++) {
            oacc[nt][0] *= sc0; oacc[nt][1] *= sc0;
            oacc[nt][2] *= sc1; oacc[nt][3] *= sc1;
        }

        // ---- P -> smem (per-warp rows), refragment via ldmatrix, O += P @ V ----
        float* Pw = Ps + (wid * 16) * PADR;
        #pragma unroll
        for (int nt = 0; nt < 8; nt++) {
            int c = (nt << 3) + (tig << 1);
            *(float2*)&Pw[gid * PADR + c]       = make_float2(sacc[nt][0], sacc[nt][1]);
            *(float2*)&Pw[(gid + 8) * PADR + c] = make_float2(sacc[nt][2], sacc[nt][3]);
        }
        __syncwarp();
        {
            uint32_t pA = smem_u32(Ps) + aOffF * 4;
            uint32_t vA = smem_u32(Vt) + bOffF * 4;
            #pragma unroll
            for (int ks = 0; ks < 8; ks++) {
                uint32_t a[4];
                ldsm4(a, pA + ks * 32);
                #pragma unroll
                for (int p = 0; p < 4; p++) {
                    uint32_t bb[4];
                    ldsm4(bb, vA + ks * 32 + p * 16 * PADR * 4);
                    mma_tf32(oacc[2 * p],     a, bb[0], bb[1]);
                    mma_tf32(oacc[2 * p + 1], a, bb[2], bb[3]);
                }
            }
        }
    }

    // ---- epilogue: normalize, write ----
    float rl0 = 1.f / l0r, rl1 = 1.f / l1r;
    const int r0 = m0 + wid * 16 + gid;
    #pragma unroll
    for (int nt = 0; nt < 8; nt++) {
        int c = h * HDIM + (nt << 3) + (tig << 1);
        *(float2*)&o[(long long)r0 * D_DIM + c] =
            make_float2(oacc[nt][0] * rl0, oacc[nt][1] * rl0);
        *(float2*)&o[(long long)(r0 + 8) * D_DIM + c] =
            make_float2(oacc[nt][2] * rl1, oacc[nt][3] * rl1);
    }
}

// ---------------- tf32 mma.sync GEMM, ldmatrix fragments ----------------
// C[128x128 tile] = A[M,K] * B[N,K]^T. 8 warps (4m x 2n), warp tile 32x64.
__global__ __launch_bounds__(256, 2) void gemm_mma(
    const float* __restrict__ A, int lda,
    const float* __restrict__ B, int ldb,
    float* __restrict__ C, int ldc,
    int K,
    const float* __restrict__ bias,
    const float* __restrict__ resid,
    int epi)
{
    constexpr int ST  = 3;
    constexpr int PAD = 36;
    constexpr int ASZ = 128 * PAD;
    constexpr int STF = ASZ + 128 * PAD;

    extern __shared__ float sm[];
    const int tid  = threadIdx.x;
    const int wid  = tid >> 5, lane = tid & 31;
    const int gid  = lane >> 2, tig = lane & 3;
    const int wm   = wid & 3,  wn  = wid >> 2;

    A += (long long)(blockIdx.y * 128) * lda;
    B += (long long)(blockIdx.x * 128) * ldb;

    const int nch = K >> 5;

    // ldmatrix lane offsets (floats)
    const int aOffF = ((wm << 5) + (lane & 15)) * PAD + ((lane >> 4) << 2);
    const int bOffF = ((wn << 6) + ((lane >> 4) << 3) + (lane & 7)) * PAD +
                      (((lane >> 3) & 1) << 2);

    auto load_chunk = [&](int c) {
        float* s = sm + (c % ST) * STF;
        const long long k0 = (long long)c << 5;
        uint32_t sA = smem_u32(s);
        #pragma unroll
        for (int i = 0; i < 4; i++) {
            int v = tid + (i << 8);
            int r = v >> 3, kq = v & 7;
            cp_async16(sA + (uint32_t)(r * PAD + (kq << 2)) * 4,
                       A + (long long)r * lda + k0 + (kq << 2));
        }
        uint32_t sB = smem_u32(s + ASZ);
        #pragma unroll
        for (int i = 0; i < 4; i++) {
            int v = tid + (i << 8);
            int r = v >> 3, kq = v & 7;
            cp_async16(sB + (uint32_t)(r * PAD + (kq << 2)) * 4,
                       B + (long long)r * ldb + k0 + (kq << 2));
        }
        cp_commit();
    };

    float acc[2][8][4];
    #pragma unroll
    for (int mt = 0; mt < 2; mt++)
        #pragma unroll
        for (int nt = 0; nt < 8; nt++)
            #pragma unroll
            for (int j = 0; j < 4; j++) acc[mt][nt][j] = 0.f;

    const int npro = (nch < ST - 1) ? nch : ST - 1;
    for (int s = 0; s < npro; s++) load_chunk(s);

    for (int c = 0; c < nch; c++) {
        int pend = nch - 1 - c;
        if (pend > ST - 2) pend = ST - 2;
        cp_wait(pend);
        __syncthreads();
        int ln = c + ST - 1;
        if (ln < nch) load_chunk(ln);

        uint32_t sbase = smem_u32(sm + (c % ST) * STF);
        uint32_t aA = sbase + aOffF * 4;
        uint32_t bA = sbase + (ASZ + bOffF) * 4;
        #pragma unroll
        for (int ks = 0; ks < 4; ks++) {
            uint32_t a0[4], a1[4], bb[4][4];
            ldsm4(a0, aA + ks * 32);
            ldsm4(a1, aA + ks * 32 + 16 * PAD * 4);
            #pragma unroll
            for (int p = 0; p < 4; p++)
                ldsm4(bb[p], bA + ks * 32 + p * 16 * PAD * 4);
            #pragma unroll
            for (int p = 0; p < 4; p++) {
                mma_tf32(acc[0][2 * p],     a0, bb[p][0], bb[p][1]);
                mma_tf32(acc[0][2 * p + 1], a0, bb[p][2], bb[p][3]);
                mma_tf32(acc[1][2 * p],     a1, bb[p][0], bb[p][1]);
                mma_tf32(acc[1][2 * p + 1], a1, bb[p][2], bb[p][3]);
            }
        }
    }

    // ---------------- epilogue ----------------
    const int n0 = blockIdx.x * 128 + (wn << 6);
    const int m0 = blockIdx.y * 128 + (wm << 5);
    #pragma unroll
    for (int mt = 0; mt < 2; mt++) {
        #pragma unroll
        for (int half = 0; half < 2; half++) {
            const int row = m0 + (mt << 4) + gid + (half << 3);
            float*       Crow = C + (long long)row * ldc;
            const float* Rrow = resid ? (resid + (long long)row * ldc) : nullptr;
            #pragma unroll
            for (int nt = 0; nt < 8; nt++) {
                const int col = n0 + (nt << 3) + (tig << 1);
                float v0 = acc[mt][nt][(half << 1) + 0];
                float v1 = acc[mt][nt][(half << 1) + 1];
                if (epi != EPI_NONE) { v0 += bias[col]; v1 += bias[col + 1]; }
                if (epi == EPI_BIAS_RES) {
                    float2 rr = *(const float2*)(Rrow + col);
                    v0 += rr.x; v1 += rr.y;
                } else if (epi == EPI_BIAS_GELU) {
                    v0 = gelu_exact(v0); v1 = gelu_exact(v1);
                }
                *(float2*)(Crow + col) = make_float2(v0, v1);
            }
        }
    }
}

// ---------------- launcher ----------------
extern "C" void kernel_launch(void* const* d_in, const int* in_sizes, int n_in,
                              void* d_out, int out_size)
{
    (void)in_sizes; (void)n_in; (void)out_size;
    const float* x    = (const float*)d_in[0];
    const float* ln1s = (const float*)d_in[1];
    const float* ln1b = (const float*)d_in[2];
    const float* ln2s = (const float*)d_in[3];
    const float* ln2b = (const float*)d_in[4];
    const float* Wq   = (const float*)d_in[5];
    const float* bq   = (const float*)d_in[6];
    const float* Wk   = (const float*)d_in[7];
    const float* bk   = (const float*)d_in[8];
    const float* Wv   = (const float*)d_in[9];
    const float* bv   = (const float*)d_in[10];
    const float* Wo   = (const float*)d_in[11];
    const float* bo   = (const float*)d_in[12];
    const float* W1   = (const float*)d_in[13];
    const float* b1   = (const float*)d_in[14];
    const float* W2   = (const float*)d_in[15];
    const float* b2   = (const float*)d_in[16];
    float* out = (float*)d_out;

    float *y, *qkv, *o, *x1, *ffn;
    float *Wqkv, *bqkv, *WoT, *W1T, *W2T, *vT;
    cudaGetSymbolAddress((void**)&y,    g_y);
    cudaGetSymbolAddress((void**)&qkv,  g_qkv);
    cudaGetSymbolAddress((void**)&o,    g_o);
    cudaGetSymbolAddress((void**)&x1,   g_x1);
    cudaGetSymbolAddress((void**)&ffn,  g_ffn);
    cudaGetSymbolAddress((void**)&Wqkv, g_Wqkv);
    cudaGetSymbolAddress((void**)&bqkv, g_bqkv);
    cudaGetSymbolAddress((void**)&WoT,  g_WoT);
    cudaGetSymbolAddress((void**)&W1T,  g_W1T);
    cudaGetSymbolAddress((void**)&W2T,  g_W2T);
    cudaGetSymbolAddress((void**)&vT,   g_vT);

    const int SMEMG  = 3 * (128 + 128) * 36 * 4;            // 110592
    const int SMEMFL = (4 * 64 * 68 + 128 * 68) * 4;        // 104448
    cudaFuncSetAttribute(gemm_mma,     cudaFuncAttributeMaxDynamicSharedMemorySize, SMEMG);
    cudaFuncSetAttribute(flash_kernel, cudaFuncAttributeMaxDynamicSharedMemorySize, SMEMFL);

    dim3 tb(32, 8);

    // 0) LN1
    ln_kernel<<<S_LEN, 256>>>(x, ln1s, ln1b, y);

    // 1-3) Wq/Wk/Wv -> concatenated [3072][1024]
    transpose_kernel<<<dim3(32, 32), tb>>>(Wq, D_DIM, Wqkv,                     D_DIM);
    transpose_kernel<<<dim3(32, 32), tb>>>(Wk, D_DIM, Wqkv + 1024 * D_DIM,     D_DIM);
    transpose_kernel<<<dim3(32, 32), tb>>>(Wv, D_DIM, Wqkv + 2 * 1024 * D_DIM, D_DIM);

    // 4) bias concat
    concat3_kernel<<<QKV_N / 256, 256>>>(bq, bk, bv, bqkv);

    // 5) fused QKV projection (profiled launch: -s 5)
    gemm_mma<<<dim3(QKV_N / 128, S_LEN / 128), 256, SMEMG>>>(
        y, D_DIM, Wqkv, D_DIM, qkv, QKV_N, D_DIM, bqkv, nullptr, EPI_BIAS);

    // 6-7) RoPE (1/sqrt(HD) folded into q)
    rope_kernel<<<dim3(S_LEN, NH), 32>>>(qkv,        QKV_N, 0.125f);
    rope_kernel<<<dim3(S_LEN, NH), 32>>>(qkv + 1024, QKV_N, 1.0f);

    // 8) V^T for flash PV operand (v = qkv cols 2048..3071)
    transpose_kernel<<<dim3(32, 128), tb>>>(qkv + 2048, QKV_N, vT, S_LEN);

    // 9) fused attention
    flash_kernel<<<dim3(S_LEN / 128, NH), 256, SMEMFL>>>(qkv, qkv + 1024, QKV_N, vT, o);

    // 10) WoT
    transpose_kernel<<<dim3(32, 32), tb>>>(Wo, D_DIM, WoT, D_DIM);

    // 11) x1 = o @ Wo + bo + x
    gemm_mma<<<dim3(D_DIM / 128, S_LEN / 128), 256, SMEMG>>>(
        o, D_DIM, WoT, D_DIM, x1, D_DIM, D_DIM, bo, x, EPI_BIAS_RES);

    // 12) LN2
    ln_kernel<<<S_LEN, 256>>>(x1, ln2s, ln2b, y);

    // 13) W1T
    transpose_kernel<<<dim3(128, 32), tb>>>(W1, FF_D, W1T, D_DIM);

    // 14) ffn = gelu(y @ W1 + b1)
    gemm_mma<<<dim3(FF_D / 128, S_LEN / 128), 256, SMEMG>>>(
        y, D_DIM, W1T, D_DIM, ffn, FF_D, D_DIM, b1, nullptr, EPI_BIAS_GELU);

    // 15) W2T
    transpose_kernel<<<dim3(32, 128), tb>>>(W2, D_DIM, W2T, FF_D);

    // 16) out = ffn @ W2 + b2 + x1
    gemm_mma<<<dim3(D_DIM / 128, S_LEN / 128), 256, SMEMG>>>(
        ffn, FF_D, W2T, FF_D, out, D_DIM, FF_D, b2, x1, EPI_BIAS_RES);
}

// round 9
// speedup vs baseline: 7.2037x; 1.5804x over previous
#include <cuda_runtime.h>
#include <cuda_fp16.h>
#include <cstdint>
#include <math.h>

// Problem constants
#define S_LEN 4096
#define D_DIM 1024
#define NH    16
#define HDIM  64
#define FF_D  4096
#define KT    64
#define QKV_N 3072

#define EPI_NONE      0
#define EPI_BIAS      1
#define EPI_BIAS_RES  2
#define EPI_BIAS_GELU 3

// ---------------- scratch (device globals: allocation-free rule) ----------------
__device__ __half g_y   [S_LEN * D_DIM];
__device__ __half g_qkv [S_LEN * QKV_N];             // [S][3072]: q | k | v
__device__ __half g_o   [S_LEN * D_DIM];
__device__ __half g_ffn [(long long)S_LEN * FF_D];
__device__ __half g_Wqkv[(long long)QKV_N * D_DIM];  // [3072][1024] (N,K)
__device__ __half g_WoT [D_DIM * D_DIM];
__device__ __half g_W1T [(long long)FF_D * D_DIM];
__device__ __half g_W2T [(long long)D_DIM * FF_D];
__device__ __half g_vT  [(long long)D_DIM * S_LEN];
__device__ float  g_x1  [S_LEN * D_DIM];
__device__ float  g_bqkv[QKV_N];

// ---------------- helpers ----------------
__device__ __forceinline__ uint32_t smem_u32(const void* p) {
    uint32_t a;
    asm("{ .reg .u64 t; cvta.to.shared.u64 t, %1; cvt.u32.u64 %0, t; }" : "=r"(a) : "l"(p));
    return a;
}
__device__ __forceinline__ void cp_async16(uint32_t s, const void* g) {
    asm volatile("cp.async.cg.shared.global [%0], [%1], 16;" :: "r"(s), "l"(g));
}
__device__ __forceinline__ void cp_commit() {
    asm volatile("cp.async.commit_group;" ::: "memory");
}
__device__ __forceinline__ void cp_wait(int n) {
    if (n == 0)      asm volatile("cp.async.wait_group 0;" ::: "memory");
    else if (n == 1) asm volatile("cp.async.wait_group 1;" ::: "memory");
    else             asm volatile("cp.async.wait_group 2;" ::: "memory");
}
__device__ __forceinline__ void ldsm4(uint32_t* r, uint32_t a) {
    asm volatile("ldmatrix.sync.aligned.m8n8.x4.shared.b16 {%0,%1,%2,%3}, [%4];"
        : "=r"(r[0]), "=r"(r[1]), "=r"(r[2]), "=r"(r[3]) : "r"(a));
}
__device__ __forceinline__ void mma_f16(float* c, const uint32_t* a,
                                        uint32_t b0, uint32_t b1) {
    asm volatile(
        "mma.sync.aligned.m16n8k16.row.col.f32.f16.f16.f32 "
        "{%0,%1,%2,%3}, {%4,%5,%6,%7}, {%8,%9}, {%0,%1,%2,%3};"
        : "+f"(c[0]), "+f"(c[1]), "+f"(c[2]), "+f"(c[3])
        : "r"(a[0]), "r"(a[1]), "r"(a[2]), "r"(a[3]), "r"(b0), "r"(b1));
}
__device__ __forceinline__ float gelu_exact(float v) {
    return 0.5f * v * (1.0f + erff(v * 0.70710678118654752f));
}

// ---------------- LayerNorm (fp32 in, fp16 out) ----------------
__global__ __launch_bounds__(256) void ln_kernel(const float* __restrict__ x,
                                                 const float* __restrict__ sc,
                                                 const float* __restrict__ bi,
                                                 __half* __restrict__ y)
{
    long long row = blockIdx.x;
    const float* xr = x + row * D_DIM;
    int c = threadIdx.x << 2;
    float4 xv = *(const float4*)(xr + c);
    float s  = xv.x + xv.y + xv.z + xv.w;
    float ss = xv.x*xv.x + xv.y*xv.y + xv.z*xv.z + xv.w*xv.w;
    #pragma unroll
    for (int off = 16; off; off >>= 1) {
        s  += __shfl_down_sync(0xffffffffu, s,  off);
        ss += __shfl_down_sync(0xffffffffu, ss, off);
    }
    __shared__ float sbuf[8], ssbuf[8];
    __shared__ float mu_s, rinv_s;
    int w = threadIdx.x >> 5, l = threadIdx.x & 31;
    if (l == 0) { sbuf[w] = s; ssbuf[w] = ss; }
    __syncthreads();
    if (threadIdx.x == 0) {
        float S = 0.f, SS = 0.f;
        #pragma unroll
        for (int i = 0; i < 8; i++) { S += sbuf[i]; SS += ssbuf[i]; }
        float mu  = S * (1.0f / D_DIM);
        float var = SS * (1.0f / D_DIM) - mu * mu;
        mu_s = mu;
        rinv_s = rsqrtf(var + 1e-6f);
    }
    __syncthreads();
    float mu = mu_s, rinv = rinv_s;
    float4 scv = *(const float4*)(sc + c);
    float4 bv  = *(const float4*)(bi + c);
    __half2 h0 = __floats2half2_rn((xv.x - mu) * rinv * scv.x + bv.x,
                                   (xv.y - mu) * rinv * scv.y + bv.y);
    __half2 h1 = __floats2half2_rn((xv.z - mu) * rinv * scv.z + bv.z,
                                   (xv.w - mu) * rinv * scv.w + bv.w);
    uint2 pk;
    pk.x = *(uint32_t*)&h0; pk.y = *(uint32_t*)&h1;
    *(uint2*)(y + row * D_DIM + c) = pk;
}

// ---------------- RoPE (half in place, row stride ld) ----------------
__global__ void rope_kernel(__half* __restrict__ buf, int ld, float scale)
{
    int c = threadIdx.x;                 // 0..31
    int s = blockIdx.x;
    int h = blockIdx.y;
    __half* p = buf + (long long)s * ld + h * HDIM;
    float freq = expf(-(float)c * (9.210340371976184f / 32.0f));
    float ang = (float)s * freq;
    float sn, cs;
    sincosf(ang, &sn, &cs);
    float x1 = __half2float(p[c]), x2 = __half2float(p[c + 32]);
    p[c]      = __float2half_rn((x1 * cs - x2 * sn) * scale);
    p[c + 32] = __float2half_rn((x2 * cs + x1 * sn) * scale);
}

// ---------------- concat 3 bias vectors ----------------
__global__ void concat3_kernel(const float* __restrict__ a, const float* __restrict__ b,
                               const float* __restrict__ c, float* __restrict__ out)
{
    int i = blockIdx.x * 256 + threadIdx.x;
    out[i] = (i < 1024) ? a[i] : ((i < 2048) ? b[i - 1024] : c[i - 2048]);
}

// ---------------- transpose fp32 -> fp16: out[c][r] = in[r][c] ----------------
__global__ void transpose_wh(const float* __restrict__ in, int ldin,
                             __half* __restrict__ out, int ldout)
{
    __shared__ float t[32][33];
    int c0 = blockIdx.x * 32, r0 = blockIdx.y * 32;
    #pragma unroll
    for (int i = 0; i < 32; i += 8)
        t[threadIdx.y + i][threadIdx.x] =
            in[(long long)(r0 + threadIdx.y + i) * ldin + c0 + threadIdx.x];
    __syncthreads();
    #pragma unroll
    for (int i = 0; i < 32; i += 8)
        out[(long long)(c0 + threadIdx.y + i) * ldout + r0 + threadIdx.x] =
            __float2half_rn(t[threadIdx.x][threadIdx.y + i]);
}

// ---------------- transpose fp16 -> fp16 ----------------
__global__ void transpose_hh(const __half* __restrict__ in, int ldin,
                             __half* __restrict__ out, int ldout)
{
    __shared__ __half t[32][34];
    int c0 = blockIdx.x * 32, r0 = blockIdx.y * 32;
    #pragma unroll
    for (int i = 0; i < 32; i += 8)
        t[threadIdx.y + i][threadIdx.x] =
            in[(long long)(r0 + threadIdx.y + i) * ldin + c0 + threadIdx.x];
    __syncthreads();
    #pragma unroll
    for (int i = 0; i < 32; i += 8)
        out[(long long)(c0 + threadIdx.y + i) * ldout + r0 + threadIdx.x] =
            t[threadIdx.x][threadIdx.y + i];
}

// ---------------- fused flash attention (fp16 operands, fp32 accum) ----------------
// One CTA = (128 q-rows, one head). 8 warps, each owns 16 q-rows.
// K/V tiles of 64 keys, double-buffered cp.async. Online softmax, O in regs.
// q pre-scaled by 1/sqrt(HD); vt is V^T laid out [h*HD+d][s], half.
__global__ __launch_bounds__(256, 2) void flash_kernel(
    const __half* __restrict__ q, const __half* __restrict__ k, int ldqk,
    const __half* __restrict__ vt, __half* __restrict__ o)
{
    constexpr int PADH = 72;                 // halves per smem row (64 + 8)
    constexpr int TSZ  = 64 * PADH;          // halves
    extern __shared__ __half smh[];
    __half* Ks = smh;                        // [2][64][PADH]
    __half* Vs = smh + 2 * TSZ;              // [2][64][PADH]
    __half* Ps = smh + 4 * TSZ;              // [128][PADH] (Q staging, then P)

    const int tid  = threadIdx.x;
    const int wid  = tid >> 5, lane = tid & 31;
    const int gid  = lane >> 2, tig = lane & 3;
    const int h    = blockIdx.y;
    const int m0   = blockIdx.x * 128;

    // ldmatrix lane offsets (halves)
    const int aOffH = (wid * 16 + (lane & 15)) * PADH + ((lane >> 4) << 3);
    const int bOffH = (lane & 15) * PADH + ((lane >> 4) << 3);

    // ---- stage Q tile (128 x 64 halves), extract fragments ----
    {
        uint32_t sQ = smem_u32(Ps);
        #pragma unroll
        for (int i = 0; i < 4; i++) {        // 128 rows x 8 x 16B
            int t = tid + (i << 8);
            int r = t >> 3, kq = t & 7;
            cp_async16(sQ + (uint32_t)(r * PADH + (kq << 3)) * 2,
                       q + (long long)(m0 + r) * ldqk + h * HDIM + (kq << 3));
        }
        cp_commit();
    }
    cp_wait(0);
    __syncthreads();

    uint32_t qf[4][4];
    {
        uint32_t qA = smem_u32(Ps) + aOffH * 2;
        #pragma unroll
        for (int ks = 0; ks < 4; ks++) ldsm4(qf[ks], qA + ks * 32);
    }
    __syncthreads();                         // Ps now reusable for P

    float oacc[8][4] = {};
    float m0r = -1e30f, m1r = -1e30f;
    float l0r = 0.f,    l1r = 0.f;

    auto load_tile = [&](int kt) {
        int st = kt & 1;
        uint32_t sK = smem_u32(Ks + st * TSZ);
        uint32_t sV = smem_u32(Vs + st * TSZ);
        const long long j0 = (long long)kt * KT;
        #pragma unroll
        for (int i = 0; i < 2; i++) {        // K: 64 rows x 8 x 16B
            int t = tid + (i << 8);
            int r = t >> 3, kq = t & 7;
            cp_async16(sK + (uint32_t)(r * PADH + (kq << 3)) * 2,
                       k + (j0 + r) * ldqk + h * HDIM + (kq << 3));
        }
        #pragma unroll
        for (int i = 0; i < 2; i++) {        // V^T: rows = d, cols = j
            int t = tid + (i << 8);
            int r = t >> 3, kq = t & 7;
            cp_async16(sV + (uint32_t)(r * PADH + (kq << 3)) * 2,
                       vt + (long long)(h * HDIM + r) * S_LEN + j0 + (kq << 3));
        }
        cp_commit();
    };

    load_tile(0);

    for (int kt = 0; kt < S_LEN / KT; kt++) {
        cp_wait(0);
        __syncthreads();
        if (kt + 1 < S_LEN / KT) load_tile(kt + 1);

        const __half* Kt = Ks + (kt & 1) * TSZ;
        const __half* Vt = Vs + (kt & 1) * TSZ;

        // ---- S = Q @ K^T (16 x 64 per warp) ----
        float sacc[8][4] = {};
        {
            uint32_t kA = smem_u32(Kt) + bOffH * 2;
            #pragma unroll
            for (int ks = 0; ks < 4; ks++) {
                #pragma unroll
                for (int g = 0; g < 4; g++) {
                    uint32_t bb[4];
                    ldsm4(bb, kA + ks * 32 + g * 16 * PADH * 2);
                    mma_f16(sacc[2 * g],     qf[ks], bb[0], bb[2]);
                    mma_f16(sacc[2 * g + 1], qf[ks], bb[1], bb[3]);
                }
            }
        }

        // ---- online softmax ----
        float mx0 = -1e30f, mx1 = -1e30f;
        #pragma unroll
        for (int nt = 0; nt < 8; nt++) {
            mx0 = fmaxf(mx0, fmaxf(sacc[nt][0], sacc[nt][1]));
            mx1 = fmaxf(mx1, fmaxf(sacc[nt][2], sacc[nt][3]));
        }
        mx0 = fmaxf(mx0, __shfl_xor_sync(0xffffffffu, mx0, 1));
        mx0 = fmaxf(mx0, __shfl_xor_sync(0xffffffffu, mx0, 2));
        mx1 = fmaxf(mx1, __shfl_xor_sync(0xffffffffu, mx1, 1));
        mx1 = fmaxf(mx1, __shfl_xor_sync(0xffffffffu, mx1, 2));
        float mn0 = fmaxf(m0r, mx0), mn1 = fmaxf(m1r, mx1);
        float sc0 = __expf(m0r - mn0), sc1 = __expf(m1r - mn1);
        m0r = mn0; m1r = mn1;

        float rs0 = 0.f, rs1 = 0.f;
        #pragma unroll
        for (int nt = 0; nt < 8; nt++) {
            sacc[nt][0] = __expf(sacc[nt][0] - mn0);
            sacc[nt][1] = __expf(sacc[nt][1] - mn0);
            sacc[nt][2] = __expf(sacc[nt][2] - mn1);
            sacc[nt][3] = __expf(sacc[nt][3] - mn1);
            rs0 += sacc[nt][0] + sacc[nt][1];
            rs1 += sacc[nt][2] + sacc[nt][3];
        }
        rs0 += __shfl_xor_sync(0xffffffffu, rs0, 1);
        rs0 += __shfl_xor_sync(0xffffffffu, rs0, 2);
        rs1 += __shfl_xor_sync(0xffffffffu, rs1, 1);
        rs1 += __shfl_xor_sync(0xffffffffu, rs1, 2);
        l0r = l0r * sc0 + rs0;
        l1r = l1r * sc1 + rs1;

        #pragma unroll
        for (int nt = 0; nt < 8; nt++) {
            oacc[nt][0] *= sc0; oacc[nt][1] *= sc0;
            oacc[nt][2] *= sc1; oacc[nt][3] *= sc1;
        }

        // ---- P -> smem (half, per-warp rows), refragment, O += P @ V ----
        __half* Pw = Ps + (wid * 16) * PADH;
        #pragma unroll
        for (int nt = 0; nt < 8; nt++) {
            int c = (nt << 3) + (tig << 1);
            *(__half2*)&Pw[gid * PADH + c] =
                __floats2half2_rn(sacc[nt][0], sacc[nt][1]);
            *(__half2*)&Pw[(gid + 8) * PADH + c] =
                __floats2half2_rn(sacc[nt][2], sacc[nt][3]);
        }
        __syncwarp();
        {
            uint32_t pA = smem_u32(Ps) + aOffH * 2;
            uint32_t vA = smem_u32(Vt) + bOffH * 2;
            #pragma unroll
            for (int ks = 0; ks < 4; ks++) {
                uint32_t a[4];
                ldsm4(a, pA + ks * 32);
                #pragma unroll
                for (int g = 0; g < 4; g++) {
                    uint32_t bb[4];
                    ldsm4(bb, vA + ks * 32 + g * 16 * PADH * 2);
                    mma_f16(oacc[2 * g],     a, bb[0], bb[2]);
                    mma_f16(oacc[2 * g + 1], a, bb[1], bb[3]);
                }
            }
        }
    }

    // ---- epilogue: normalize, write half ----
    float rl0 = 1.f / l0r, rl1 = 1.f / l1r;
    const int r0 = m0 + wid * 16 + gid;
    #pragma unroll
    for (int nt = 0; nt < 8; nt++) {
        int c = h * HDIM + (nt << 3) + (tig << 1);
        *(__half2*)&o[(long long)r0 * D_DIM + c] =
            __floats2half2_rn(oacc[nt][0] * rl0, oacc[nt][1] * rl0);
        *(__half2*)&o[(long long)(r0 + 8) * D_DIM + c] =
            __floats2half2_rn(oacc[nt][2] * rl1, oacc[nt][3] * rl1);
    }
}

// ---------------- fp16 mma.sync GEMM ----------------
// C[128x128 tile] = A[M,K]h * B[N,K]h^T, fp32 accum. 8 warps (4m x 2n), warp 32x64.
// K-chunk 64 halves (128B rows). If Ch != nullptr, write half output, else fp32 C.
__global__ __launch_bounds__(256, 2) void gemm_h(
    const __half* __restrict__ A, int lda,
    const __half* __restrict__ B, int ldb,
    float* __restrict__ C, __half* __restrict__ Ch, int ldc,
    int K,
    const float* __restrict__ bias,
    const float* __restrict__ resid,
    int epi)
{
    constexpr int ST   = 3;
    constexpr int PADH = 72;                 // halves per row (64 + 8)
    constexpr int ASZ  = 128 * PADH;         // halves
    constexpr int STH  = 2 * ASZ;

    extern __shared__ __half smh[];
    const int tid  = threadIdx.x;
    const int wid  = tid >> 5, lane = tid & 31;
    const int gid  = lane >> 2, tig = lane & 3;
    const int wm   = wid & 3,  wn  = wid >> 2;

    A += (long long)(blockIdx.y * 128) * lda;
    B += (long long)(blockIdx.x * 128) * ldb;

    const int nch = K >> 6;

    // ldmatrix lane offsets (halves)
    const int aOffH = ((wm << 5) + (lane & 15)) * PADH + ((lane >> 4) << 3);
    const int bOffH = ((wn << 6) + (lane & 15)) * PADH + ((lane >> 4) << 3);

    auto load_chunk = [&](int c) {
        __half* s = smh + (c % ST) * STH;
        const long long k0 = (long long)c << 6;
        uint32_t sA = smem_u32(s);
        #pragma unroll
        for (int i = 0; i < 4; i++) {        // A: 128 rows x 8 x 16B
            int v = tid + (i << 8);
            int r = v >> 3, kq = v & 7;
            cp_async16(sA + (uint32_t)(r * PADH + (kq << 3)) * 2,
                       A + (long long)r * lda + k0 + (kq << 3));
        }
        uint32_t sB = smem_u32(s + ASZ);
        #pragma unroll
        for (int i = 0; i < 4; i++) {
            int v = tid + (i << 8);
            int r = v >> 3, kq = v & 7;
            cp_async16(sB + (uint32_t)(r * PADH + (kq << 3)) * 2,
                       B + (long long)r * ldb + k0 + (kq << 3));
        }
        cp_commit();
    };

    float acc[2][8][4];
    #pragma unroll
    for (int mt = 0; mt < 2; mt++)
        #pragma unroll
        for (int nt = 0; nt < 8; nt++)
            #pragma unroll
            for (int j = 0; j < 4; j++) acc[mt][nt][j] = 0.f;

    const int npro = (nch < ST - 1) ? nch : ST - 1;
    for (int s = 0; s < npro; s++) load_chunk(s);

    for (int c = 0; c < nch; c++) {
        int pend = nch - 1 - c;
        if (pend > ST - 2) pend = ST - 2;
        cp_wait(pend);
        __syncthreads();
        int ln = c + ST - 1;
        if (ln < nch) load_chunk(ln);

        uint32_t sbase = smem_u32(smh + (c % ST) * STH);
        uint32_t aA = sbase + aOffH * 2;
        uint32_t bA = sbase + (ASZ + bOffH) * 2;
        #pragma unroll
        for (int ks = 0; ks < 4; ks++) {     // 4 x k16
            uint32_t a0[4], a1[4];
            ldsm4(a0, aA + ks * 32);
            ldsm4(a1, aA + ks * 32 + 16 * PADH * 2);
            #pragma unroll
            for (int g = 0; g < 4; g++) {
                uint32_t bb[4];
                ldsm4(bb, bA + ks * 32 + g * 16 * PADH * 2);
                mma_f16(acc[0][2 * g],     a0, bb[0], bb[2]);
                mma_f16(acc[0][2 * g + 1], a0, bb[1], bb[3]);
                mma_f16(acc[1][2 * g],     a1, bb[0], bb[2]);
                mma_f16(acc[1][2 * g + 1], a1, bb[1], bb[3]);
            }
        }
    }

    // ---------------- epilogue ----------------
    const int n0 = blockIdx.x * 128 + (wn << 6);
    const int m0 = blockIdx.y * 128 + (wm << 5);
    #pragma unroll
    for (int mt = 0; mt < 2; mt++) {
        #pragma unroll
        for (int half_ = 0; half_ < 2; half_++) {
            const int row = m0 + (mt << 4) + gid + (half_ << 3);
            const float* Rrow = resid ? (resid + (long long)row * ldc) : nullptr;
            #pragma unroll
            for (int nt = 0; nt < 8; nt++) {
                const int col = n0 + (nt << 3) + (tig << 1);
                float v0 = acc[mt][nt][(half_ << 1) + 0];
                float v1 = acc[mt][nt][(half_ << 1) + 1];
                if (epi != EPI_NONE) { v0 += bias[col]; v1 += bias[col + 1]; }
                if (epi == EPI_BIAS_RES) {
                    float2 rr = *(const float2*)(Rrow + col);
                    v0 += rr.x; v1 += rr.y;
                } else if (epi == EPI_BIAS_GELU) {
                    v0 = gelu_exact(v0); v1 = gelu_exact(v1);
                }
                if (Ch) {
                    *(__half2*)(Ch + (long long)row * ldc + col) =
                        __floats2half2_rn(v0, v1);
                } else {
                    *(float2*)(C + (long long)row * ldc + col) = make_float2(v0, v1);
                }
            }
        }
    }
}

// ---------------- launcher ----------------
extern "C" void kernel_launch(void* const* d_in, const int* in_sizes, int n_in,
                              void* d_out, int out_size)
{
    (void)in_sizes; (void)n_in; (void)out_size;
    const float* x    = (const float*)d_in[0];
    const float* ln1s = (const float*)d_in[1];
    const float* ln1b = (const float*)d_in[2];
    const float* ln2s = (const float*)d_in[3];
    const float* ln2b = (const float*)d_in[4];
    const float* Wq   = (const float*)d_in[5];
    const float* bq   = (const float*)d_in[6];
    const float* Wk   = (const float*)d_in[7];
    const float* bk   = (const float*)d_in[8];
    const float* Wv   = (const float*)d_in[9];
    const float* bv   = (const float*)d_in[10];
    const float* Wo   = (const float*)d_in[11];
    const float* bo   = (const float*)d_in[12];
    const float* W1   = (const float*)d_in[13];
    const float* b1   = (const float*)d_in[14];
    const float* W2   = (const float*)d_in[15];
    const float* b2   = (const float*)d_in[16];
    float* out = (float*)d_out;

    __half *y, *qkv, *o, *ffn, *Wqkv, *WoT, *W1T, *W2T, *vT;
    float  *x1, *bqkv;
    cudaGetSymbolAddress((void**)&y,    g_y);
    cudaGetSymbolAddress((void**)&qkv,  g_qkv);
    cudaGetSymbolAddress((void**)&o,    g_o);
    cudaGetSymbolAddress((void**)&ffn,  g_ffn);
    cudaGetSymbolAddress((void**)&Wqkv, g_Wqkv);
    cudaGetSymbolAddress((void**)&WoT,  g_WoT);
    cudaGetSymbolAddress((void**)&W1T,  g_W1T);
    cudaGetSymbolAddress((void**)&W2T,  g_W2T);
    cudaGetSymbolAddress((void**)&vT,   g_vT);
    cudaGetSymbolAddress((void**)&x1,   g_x1);
    cudaGetSymbolAddress((void**)&bqkv, g_bqkv);

    const int SMEMG  = 3 * 2 * 128 * 72 * 2;               // 110592
    const int SMEMFL = (4 * 64 * 72 + 128 * 72) * 2;       // 55296
    cudaFuncSetAttribute(gemm_h,       cudaFuncAttributeMaxDynamicSharedMemorySize, SMEMG);
    cudaFuncSetAttribute(flash_kernel, cudaFuncAttributeMaxDynamicSharedMemorySize, SMEMFL);

    dim3 tb(32, 8);

    // 0) LN1 -> y (half)
    ln_kernel<<<S_LEN, 256>>>(x, ln1s, ln1b, y);

    // 1-3) Wq/Wk/Wv -> concatenated half [3072][1024]
    transpose_wh<<<dim3(32, 32), tb>>>(Wq, D_DIM, Wqkv,                     D_DIM);
    transpose_wh<<<dim3(32, 32), tb>>>(Wk, D_DIM, Wqkv + 1024 * D_DIM,     D_DIM);
    transpose_wh<<<dim3(32, 32), tb>>>(Wv, D_DIM, Wqkv + 2 * 1024 * D_DIM, D_DIM);

    // 4) bias concat (fp32)
    concat3_kernel<<<QKV_N / 256, 256>>>(bq, bk, bv, bqkv);

    // 5) fused QKV projection -> qkv (half)
    gemm_h<<<dim3(QKV_N / 128, S_LEN / 128), 256, SMEMG>>>(
        y, D_DIM, Wqkv, D_DIM, nullptr, qkv, QKV_N, D_DIM, bqkv, nullptr, EPI_BIAS);

    // 6-7) RoPE (1/sqrt(HD) folded into q)
    rope_kernel<<<dim3(S_LEN, NH), 32>>>(qkv,        QKV_N, 0.125f);
    rope_kernel<<<dim3(S_LEN, NH), 32>>>(qkv + 1024, QKV_N, 1.0f);

    // 8) V^T (half) for flash PV operand
    transpose_hh<<<dim3(32, 128), tb>>>(qkv + 2048, QKV_N, vT, S_LEN);

    // 9) fused attention -> o (half)
    flash_kernel<<<dim3(S_LEN / 128, NH), 256, SMEMFL>>>(qkv, qkv + 1024, QKV_N, vT, o);

    // 10) WoT (half)
    transpose_wh<<<dim3(32, 32), tb>>>(Wo, D_DIM, WoT, D_DIM);

    // 11) x1 = o @ Wo + bo + x  (fp32 out)
    gemm_h<<<dim3(D_DIM / 128, S_LEN / 128), 256, SMEMG>>>(
        o, D_DIM, WoT, D_DIM, x1, nullptr, D_DIM, D_DIM, bo, x, EPI_BIAS_RES);

    // 12) LN2 -> y (half)
    ln_kernel<<<S_LEN, 256>>>(x1, ln2s, ln2b, y);

    // 13) W1T (half)
    transpose_wh<<<dim3(128, 32), tb>>>(W1, FF_D, W1T, D_DIM);

    // 14) ffn = gelu(y @ W1 + b1) (half out)
    gemm_h<<<dim3(FF_D / 128, S_LEN / 128), 256, SMEMG>>>(
        y, D_DIM, W1T, D_DIM, nullptr, ffn, FF_D, D_DIM, b1, nullptr, EPI_BIAS_GELU);

    // 15) W2T (half)
    transpose_wh<<<dim3(32, 128), tb>>>(W2, D_DIM, W2T, FF_D);

    // 16) out = ffn @ W2 + b2 + x1 (fp32 out)
    gemm_h<<<dim3(D_DIM / 128, S_LEN / 128), 256, SMEMG>>>(
        ffn, FF_D, W2T, FF_D, out, nullptr, D_DIM, FF_D, b2, x1, EPI_BIAS_RES);
}

// round 10
// speedup vs baseline: 7.5714x; 1.0510x over previous
#include <cuda_runtime.h>
#include <cuda_fp16.h>
#include <cstdint>
#include <math.h>

// Problem constants
#define S_LEN 4096
#define D_DIM 1024
#define NH    16
#define HDIM  64
#define FF_D  4096
#define KT    64
#define QKV_N 3072

#define EPI_NONE      0
#define EPI_BIAS      1
#define EPI_BIAS_RES  2
#define EPI_BIAS_GELU 3

// ---------------- scratch (device globals: allocation-free rule) ----------------
__device__ __half g_y   [S_LEN * D_DIM];
__device__ __half g_qkv [S_LEN * QKV_N];             // [S][3072]: q | k | v
__device__ __half g_o   [S_LEN * D_DIM];
__device__ __half g_ffn [(long long)S_LEN * FF_D];
__device__ __half g_Wqkv[(long long)D_DIM * QKV_N];  // [1024][3072] K-major
__device__ __half g_WoH [D_DIM * D_DIM];             // [1024][1024] K-major
__device__ __half g_W1H [(long long)D_DIM * FF_D];   // [1024][4096] K-major
__device__ __half g_W2H [(long long)FF_D * D_DIM];   // [4096][1024] K-major
__device__ float  g_x1  [S_LEN * D_DIM];
__device__ float  g_bqkv[QKV_N];

// ---------------- helpers ----------------
__device__ __forceinline__ uint32_t smem_u32(const void* p) {
    uint32_t a;
    asm("{ .reg .u64 t; cvta.to.shared.u64 t, %1; cvt.u32.u64 %0, t; }" : "=r"(a) : "l"(p));
    return a;
}
__device__ __forceinline__ void cp_async16(uint32_t s, const void* g) {
    asm volatile("cp.async.cg.shared.global [%0], [%1], 16;" :: "r"(s), "l"(g));
}
__device__ __forceinline__ void cp_commit() {
    asm volatile("cp.async.commit_group;" ::: "memory");
}
__device__ __forceinline__ void cp_wait(int n) {
    if (n == 0)      asm volatile("cp.async.wait_group 0;" ::: "memory");
    else if (n == 1) asm volatile("cp.async.wait_group 1;" ::: "memory");
    else             asm volatile("cp.async.wait_group 2;" ::: "memory");
}
__device__ __forceinline__ void ldsm4(uint32_t* r, uint32_t a) {
    asm volatile("ldmatrix.sync.aligned.m8n8.x4.shared.b16 {%0,%1,%2,%3}, [%4];"
        : "=r"(r[0]), "=r"(r[1]), "=r"(r[2]), "=r"(r[3]) : "r"(a));
}
__device__ __forceinline__ void ldsm4t(uint32_t* r, uint32_t a) {
    asm volatile("ldmatrix.sync.aligned.m8n8.x4.trans.shared.b16 {%0,%1,%2,%3}, [%4];"
        : "=r"(r[0]), "=r"(r[1]), "=r"(r[2]), "=r"(r[3]) : "r"(a));
}
__device__ __forceinline__ void mma_f16(float* c, const uint32_t* a,
                                        uint32_t b0, uint32_t b1) {
    asm volatile(
        "mma.sync.aligned.m16n8k16.row.col.f32.f16.f16.f32 "
        "{%0,%1,%2,%3}, {%4,%5,%6,%7}, {%8,%9}, {%0,%1,%2,%3};"
        : "+f"(c[0]), "+f"(c[1]), "+f"(c[2]), "+f"(c[3])
        : "r"(a[0]), "r"(a[1]), "r"(a[2]), "r"(a[3]), "r"(b0), "r"(b1));
}
__device__ __forceinline__ float gelu_exact(float v) {
    return 0.5f * v * (1.0f + erff(v * 0.70710678118654752f));
}

// ---------------- LayerNorm (fp32 in, fp16 out) ----------------
__global__ __launch_bounds__(256) void ln_kernel(const float* __restrict__ x,
                                                 const float* __restrict__ sc,
                                                 const float* __restrict__ bi,
                                                 __half* __restrict__ y)
{
    long long row = blockIdx.x;
    const float* xr = x + row * D_DIM;
    int c = threadIdx.x << 2;
    float4 xv = *(const float4*)(xr + c);
    float s  = xv.x + xv.y + xv.z + xv.w;
    float ss = xv.x*xv.x + xv.y*xv.y + xv.z*xv.z + xv.w*xv.w;
    #pragma unroll
    for (int off = 16; off; off >>= 1) {
        s  += __shfl_down_sync(0xffffffffu, s,  off);
        ss += __shfl_down_sync(0xffffffffu, ss, off);
    }
    __shared__ float sbuf[8], ssbuf[8];
    __shared__ float mu_s, rinv_s;
    int w = threadIdx.x >> 5, l = threadIdx.x & 31;
    if (l == 0) { sbuf[w] = s; ssbuf[w] = ss; }
    __syncthreads();
    if (threadIdx.x == 0) {
        float S = 0.f, SS = 0.f;
        #pragma unroll
        for (int i = 0; i < 8; i++) { S += sbuf[i]; SS += ssbuf[i]; }
        float mu  = S * (1.0f / D_DIM);
        float var = SS * (1.0f / D_DIM) - mu * mu;
        mu_s = mu;
        rinv_s = rsqrtf(var + 1e-6f);
    }
    __syncthreads();
    float mu = mu_s, rinv = rinv_s;
    float4 scv = *(const float4*)(sc + c);
    float4 bv  = *(const float4*)(bi + c);
    __half2 h0 = __floats2half2_rn((xv.x - mu) * rinv * scv.x + bv.x,
                                   (xv.y - mu) * rinv * scv.y + bv.y);
    __half2 h1 = __floats2half2_rn((xv.z - mu) * rinv * scv.z + bv.z,
                                   (xv.w - mu) * rinv * scv.w + bv.w);
    uint2 pk;
    pk.x = *(uint32_t*)&h0; pk.y = *(uint32_t*)&h1;
    *(uint2*)(y + row * D_DIM + c) = pk;
}

// ---------------- RoPE (half in place, row stride ld) ----------------
__global__ void rope_kernel(__half* __restrict__ buf, int ld, float scale)
{
    int c = threadIdx.x;                 // 0..31
    int s = blockIdx.x;
    int h = blockIdx.y;
    __half* p = buf + (long long)s * ld + h * HDIM;
    float freq = expf(-(float)c * (9.210340371976184f / 32.0f));
    float ang = (float)s * freq;
    float sn, cs;
    sincosf(ang, &sn, &cs);
    float x1 = __half2float(p[c]), x2 = __half2float(p[c + 32]);
    p[c]      = __float2half_rn((x1 * cs - x2 * sn) * scale);
    p[c + 32] = __float2half_rn((x2 * cs + x1 * sn) * scale);
}

// ---------------- concat 3 bias vectors ----------------
__global__ void concat3_kernel(const float* __restrict__ a, const float* __restrict__ b,
                               const float* __restrict__ c, float* __restrict__ out)
{
    int i = blockIdx.x * 256 + threadIdx.x;
    out[i] = (i < 1024) ? a[i] : ((i < 2048) ? b[i - 1024] : c[i - 2048]);
}

// ---------------- fp32 -> fp16 convert, layout-preserving with row remap ----------------
// out[k*ldout + off + n] = in[k*ncols + n];  ncols % 4 == 0
__global__ __launch_bounds__(256) void cvt_kernel(const float* __restrict__ in,
                                                  __half* __restrict__ out,
                                                  int ncols, int ldout, int off)
{
    long long i4 = (long long)blockIdx.x * 256 + threadIdx.x;   // float4 index
    int nq = ncols >> 2;
    long long k = i4 / nq;
    int n = (int)(i4 % nq) << 2;
    float4 v = *(const float4*)(in + k * ncols + n);
    __half2 h0 = __floats2half2_rn(v.x, v.y);
    __half2 h1 = __floats2half2_rn(v.z, v.w);
    uint2 pk;
    pk.x = *(uint32_t*)&h0; pk.y = *(uint32_t*)&h1;
    *(uint2*)(out + k * ldout + off + n) = pk;
}

// ---------------- fused flash attention (fp16 operands, fp32 accum) ----------------
// One CTA = (128 q-rows, one head). 8 warps, each owns 16 q-rows.
// K/V tiles of 64 keys, double-buffered cp.async. V loaded [keys][dims] and
// re-fragmented with ldmatrix.trans. Online softmax, O in regs.
__global__ __launch_bounds__(256, 2) void flash_kernel(
    const __half* __restrict__ q, const __half* __restrict__ k,
    const __half* __restrict__ v, int ldqk, __half* __restrict__ o)
{
    constexpr int PADH = 72;                 // halves per smem row (64 + 8)
    constexpr int TSZ  = 64 * PADH;          // halves
    extern __shared__ __half smh[];
    __half* Ks = smh;                        // [2][64][PADH]
    __half* Vs = smh + 2 * TSZ;              // [2][64][PADH]
    __half* Ps = smh + 4 * TSZ;              // [128][PADH] (Q staging, then P)

    const int tid  = threadIdx.x;
    const int wid  = tid >> 5, lane = tid & 31;
    const int gid  = lane >> 2, tig = lane & 3;
    const int h    = blockIdx.y;
    const int m0   = blockIdx.x * 128;

    // ldmatrix lane offsets (halves)
    const int aOffH = (wid * 16 + (lane & 15)) * PADH + ((lane >> 4) << 3);
    const int bOffH = (lane & 15) * PADH + ((lane >> 4) << 3);
    // trans offset for V ([j][d] tile -> B fragments of V^T)
    const int vOffH = ((lane & 7) + (((lane >> 3) & 1) << 3)) * PADH +
                      (((lane >> 4) & 1) << 3);

    // ---- stage Q tile (128 x 64 halves), extract fragments ----
    {
        uint32_t sQ = smem_u32(Ps);
        #pragma unroll
        for (int i = 0; i < 4; i++) {        // 128 rows x 8 x 16B
            int t = tid + (i << 8);
            int r = t >> 3, kq = t & 7;
            cp_async16(sQ + (uint32_t)(r * PADH + (kq << 3)) * 2,
                       q + (long long)(m0 + r) * ldqk + h * HDIM + (kq << 3));
        }
        cp_commit();
    }
    cp_wait(0);
    __syncthreads();

    uint32_t qf[4][4];
    {
        uint32_t qA = smem_u32(Ps) + aOffH * 2;
        #pragma unroll
        for (int ks = 0; ks < 4; ks++) ldsm4(qf[ks], qA + ks * 32);
    }
    __syncthreads();                         // Ps now reusable for P

    float oacc[8][4] = {};
    float m0r = -1e30f, m1r = -1e30f;
    float l0r = 0.f,    l1r = 0.f;

    auto load_tile = [&](int kt) {
        int st = kt & 1;
        uint32_t sK = smem_u32(Ks + st * TSZ);
        uint32_t sV = smem_u32(Vs + st * TSZ);
        const long long j0 = (long long)kt * KT;
        #pragma unroll
        for (int i = 0; i < 2; i++) {        // K: 64 rows x 8 x 16B
            int t = tid + (i << 8);
            int r = t >> 3, kq = t & 7;
            cp_async16(sK + (uint32_t)(r * PADH + (kq << 3)) * 2,
                       k + (j0 + r) * ldqk + h * HDIM + (kq << 3));
        }
        #pragma unroll
        for (int i = 0; i < 2; i++) {        // V: same [keys][dims] layout
            int t = tid + (i << 8);
            int r = t >> 3, kq = t & 7;
            cp_async16(sV + (uint32_t)(r * PADH + (kq << 3)) * 2,
                       v + (j0 + r) * ldqk + h * HDIM + (kq << 3));
        }
        cp_commit();
    };

    load_tile(0);

    for (int kt = 0; kt < S_LEN / KT; kt++) {
        cp_wait(0);
        __syncthreads();
        if (kt + 1 < S_LEN / KT) load_tile(kt + 1);

        const __half* Kt = Ks + (kt & 1) * TSZ;
        const __half* Vt = Vs + (kt & 1) * TSZ;

        // ---- S = Q @ K^T (16 x 64 per warp) ----
        float sacc[8][4] = {};
        {
            uint32_t kA = smem_u32(Kt) + bOffH * 2;
            #pragma unroll
            for (int ks = 0; ks < 4; ks++) {
                #pragma unroll
                for (int g = 0; g < 4; g++) {
                    uint32_t bb[4];
                    ldsm4(bb, kA + ks * 32 + g * 16 * PADH * 2);
                    mma_f16(sacc[2 * g],     qf[ks], bb[0], bb[2]);
                    mma_f16(sacc[2 * g + 1], qf[ks], bb[1], bb[3]);
                }
            }
        }

        // ---- online softmax ----
        float mx0 = -1e30f, mx1 = -1e30f;
        #pragma unroll
        for (int nt = 0; nt < 8; nt++) {
            mx0 = fmaxf(mx0, fmaxf(sacc[nt][0], sacc[nt][1]));
            mx1 = fmaxf(mx1, fmaxf(sacc[nt][2], sacc[nt][3]));
        }
        mx0 = fmaxf(mx0, __shfl_xor_sync(0xffffffffu, mx0, 1));
        mx0 = fmaxf(mx0, __shfl_xor_sync(0xffffffffu, mx0, 2));
        mx1 = fmaxf(mx1, __shfl_xor_sync(0xffffffffu, mx1, 1));
        mx1 = fmaxf(mx1, __shfl_xor_sync(0xffffffffu, mx1, 2));
        float mn0 = fmaxf(m0r, mx0), mn1 = fmaxf(m1r, mx1);
        float sc0 = __expf(m0r - mn0), sc1 = __expf(m1r - mn1);
        m0r = mn0; m1r = mn1;

        float rs0 = 0.f, rs1 = 0.f;
        #pragma unroll
        for (int nt = 0; nt < 8; nt++) {
            sacc[nt][0] = __expf(sacc[nt][0] - mn0);
            sacc[nt][1] = __expf(sacc[nt][1] - mn0);
            sacc[nt][2] = __expf(sacc[nt][2] - mn1);
            sacc[nt][3] = __expf(sacc[nt][3] - mn1);
            rs0 += sacc[nt][0] + sacc[nt][1];
            rs1 += sacc[nt][2] + sacc[nt][3];
        }
        rs0 += __shfl_xor_sync(0xffffffffu, rs0, 1);
        rs0 += __shfl_xor_sync(0xffffffffu, rs0, 2);
        rs1 += __shfl_xor_sync(0xffffffffu, rs1, 1);
        rs1 += __shfl_xor_sync(0xffffffffu, rs1, 2);
        l0r = l0r * sc0 + rs0;
        l1r = l1r * sc1 + rs1;

        #pragma unroll
        for (int nt = 0; nt < 8; nt++) {
            oacc[nt][0] *= sc0; oacc[nt][1] *= sc0;
            oacc[nt][2] *= sc1; oacc[nt][3] *= sc1;
        }

        // ---- P -> smem (half, per-warp rows), refragment, O += P @ V ----
        __half* Pw = Ps + (wid * 16) * PADH;
        #pragma unroll
        for (int nt = 0; nt < 8; nt++) {
            int c = (nt << 3) + (tig << 1);
            *(__half2*)&Pw[gid * PADH + c] =
                __floats2half2_rn(sacc[nt][0], sacc[nt][1]);
            *(__half2*)&Pw[(gid + 8) * PADH + c] =
                __floats2half2_rn(sacc[nt][2], sacc[nt][3]);
        }
        __syncwarp();
        {
            uint32_t pA = smem_u32(Ps) + aOffH * 2;
            uint32_t vA = smem_u32(Vt) + vOffH * 2;
            #pragma unroll
            for (int ks = 0; ks < 4; ks++) {     // ks over key chunks (MMA k)
                uint32_t a[4];
                ldsm4(a, pA + ks * 32);
                #pragma unroll
                for (int g = 0; g < 4; g++) {    // g over dim groups (MMA n)
                    uint32_t bb[4];
                    ldsm4t(bb, vA + (ks * 16 * PADH + g * 16) * 2);
                    mma_f16(oacc[2 * g],     a, bb[0], bb[1]);
                    mma_f16(oacc[2 * g + 1], a, bb[2], bb[3]);
                }
            }
        }
    }

    // ---- epilogue: normalize, write half ----
    float rl0 = 1.f / l0r, rl1 = 1.f / l1r;
    const int r0 = m0 + wid * 16 + gid;
    #pragma unroll
    for (int nt = 0; nt < 8; nt++) {
        int c = h * HDIM + (nt << 3) + (tig << 1);
        *(__half2*)&o[(long long)r0 * D_DIM + c] =
            __floats2half2_rn(oacc[nt][0] * rl0, oacc[nt][1] * rl0);
        *(__half2*)&o[(long long)(r0 + 8) * D_DIM + c] =
            __floats2half2_rn(oacc[nt][2] * rl1, oacc[nt][3] * rl1);
    }
}

// ---------------- fp16 mma.sync GEMM, B in K-major [K][N] via ldmatrix.trans ----
// C[128x128 tile] = A[M,K]h * B[K,N]h, fp32 accum. 8 warps (4m x 2n), warp 32x64.
// grid: x = m-tile, y = n-tile (consecutive CTAs share the B/weight tile in L2).
__global__ __launch_bounds__(256, 2) void gemm_h(
    const __half* __restrict__ A, int lda,
    const __half* __restrict__ Bkn, int ldb,
    float* __restrict__ C, __half* __restrict__ Ch, int ldc,
    int K,
    const float* __restrict__ bias,
    const float* __restrict__ resid,
    int epi)
{
    constexpr int ST   = 3;
    constexpr int PADH = 72;                 // A row: 64 + 8 halves
    constexpr int PADN = 136;                // B row: 128 + 8 halves
    constexpr int ASZ  = 128 * PADH;         // halves
    constexpr int BSZ  = 64 * PADN;
    constexpr int STH  = ASZ + BSZ;

    extern __shared__ __half smh[];
    const int tid  = threadIdx.x;
    const int wid  = tid >> 5, lane = tid & 31;
    const int gid  = lane >> 2, tig = lane & 3;
    const int wm   = wid & 3,  wn  = wid >> 2;

    A   += (long long)(blockIdx.x * 128) * lda;
    Bkn += blockIdx.y * 128;

    const int nch = K >> 6;

    // ldmatrix lane offsets (halves)
    const int aOffH = ((wm << 5) + (lane & 15)) * PADH + ((lane >> 4) << 3);
    const int bOffH = ((lane & 7) + (((lane >> 3) & 1) << 3)) * PADN +
                      (wn << 6) + (((lane >> 4) & 1) << 3);

    auto load_chunk = [&](int c) {
        __half* s = smh + (c % ST) * STH;
        const long long k0 = (long long)c << 6;
        uint32_t sA = smem_u32(s);
        #pragma unroll
        for (int i = 0; i < 4; i++) {        // A: 128 rows x 8 x 16B
            int v = tid + (i << 8);
            int r = v >> 3, kq = v & 7;
            cp_async16(sA + (uint32_t)(r * PADH + (kq << 3)) * 2,
                       A + (long long)r * lda + k0 + (kq << 3));
        }
        uint32_t sB = smem_u32(s + ASZ);
        #pragma unroll
        for (int i = 0; i < 4; i++) {        // B: 64 k-rows x 16 x 16B
            int v = tid + (i << 8);
            int r = v >> 4, cq = v & 15;
            cp_async16(sB + (uint32_t)(r * PADN + (cq << 3)) * 2,
                       Bkn + (k0 + r) * ldb + (cq << 3));
        }
        cp_commit();
    };

    float acc[2][8][4];
    #pragma unroll
    for (int mt = 0; mt < 2; mt++)
        #pragma unroll
        for (int nt = 0; nt < 8; nt++)
            #pragma unroll
            for (int j = 0; j < 4; j++) acc[mt][nt][j] = 0.f;

    const int npro = (nch < ST - 1) ? nch : ST - 1;
    for (int s = 0; s < npro; s++) load_chunk(s);

    for (int c = 0; c < nch; c++) {
        int pend = nch - 1 - c;
        if (pend > ST - 2) pend = ST - 2;
        cp_wait(pend);
        __syncthreads();
        int ln = c + ST - 1;
        if (ln < nch) load_chunk(ln);

        uint32_t sbase = smem_u32(smh + (c % ST) * STH);
        uint32_t aA = sbase + aOffH * 2;
        uint32_t bA = sbase + (ASZ + bOffH) * 2;
        #pragma unroll
        for (int ks = 0; ks < 4; ks++) {     // 4 x k16
            uint32_t a0[4], a1[4];
            ldsm4(a0, aA + ks * 32);
            ldsm4(a1, aA + ks * 32 + 16 * PADH * 2);
            #pragma unroll
            for (int g = 0; g < 4; g++) {    // 4 x n16
                uint32_t bb[4];
                ldsm4t(bb, bA + (ks * 16 * PADN + g * 16) * 2);
                mma_f16(acc[0][2 * g],     a0, bb[0], bb[1]);
                mma_f16(acc[0][2 * g + 1], a0, bb[2], bb[3]);
                mma_f16(acc[1][2 * g],     a1, bb[0], bb[1]);
                mma_f16(acc[1][2 * g + 1], a1, bb[2], bb[3]);
            }
        }
    }

    // ---------------- epilogue ----------------
    const int n0 = blockIdx.y * 128 + (wn << 6);
    const int m0 = blockIdx.x * 128 + (wm << 5);
    #pragma unroll
    for (int mt = 0; mt < 2; mt++) {
        #pragma unroll
        for (int half_ = 0; half_ < 2; half_++) {
            const int row = m0 + (mt << 4) + gid + (half_ << 3);
            const float* Rrow = resid ? (resid + (long long)row * ldc) : nullptr;
            #pragma unroll
            for (int nt = 0; nt < 8; nt++) {
                const int col = n0 + (nt << 3) + (tig << 1);
                float v0 = acc[mt][nt][(half_ << 1) + 0];
                float v1 = acc[mt][nt][(half_ << 1) + 1];
                if (epi != EPI_NONE) { v0 += bias[col]; v1 += bias[col + 1]; }
                if (epi == EPI_BIAS_RES) {
                    float2 rr = *(const float2*)(Rrow + col);
                    v0 += rr.x; v1 += rr.y;
                } else if (epi == EPI_BIAS_GELU) {
                    v0 = gelu_exact(v0); v1 = gelu_exact(v1);
                }
                if (Ch) {
                    *(__half2*)(Ch + (long long)row * ldc + col) =
                        __floats2half2_rn(v0, v1);
                } else {
                    *(float2*)(C + (long long)row * ldc + col) = make_float2(v0, v1);
                }
            }
        }
    }
}

// ---------------- launcher ----------------
extern "C" void kernel_launch(void* const* d_in, const int* in_sizes, int n_in,
                              void* d_out, int out_size)
{
    (void)in_sizes; (void)n_in; (void)out_size;
    const float* x    = (const float*)d_in[0];
    const float* ln1s = (const float*)d_in[1];
    const float* ln1b = (const float*)d_in[2];
    const float* ln2s = (const float*)d_in[3];
    const float* ln2b = (const float*)d_in[4];
    const float* Wq   = (const float*)d_in[5];
    const float* bq   = (const float*)d_in[6];
    const float* Wk   = (const float*)d_in[7];
    const float* bk   = (const float*)d_in[8];
    const float* Wv   = (const float*)d_in[9];
    const float* bv   = (const float*)d_in[10];
    const float* Wo   = (const float*)d_in[11];
    const float* bo   = (const float*)d_in[12];
    const float* W1   = (const float*)d_in[13];
    const float* b1   = (const float*)d_in[14];
    const float* W2   = (const float*)d_in[15];
    const float* b2   = (const float*)d_in[16];
    float* out = (float*)d_out;

    __half *y, *qkv, *o, *ffn, *Wqkv, *WoH, *W1H, *W2H;
    float  *x1, *bqkv;
    cudaGetSymbolAddress((void**)&y,    g_y);
    cudaGetSymbolAddress((void**)&qkv,  g_qkv);
    cudaGetSymbolAddress((void**)&o,    g_o);
    cudaGetSymbolAddress((void**)&ffn,  g_ffn);
    cudaGetSymbolAddress((void**)&Wqkv, g_Wqkv);
    cudaGetSymbolAddress((void**)&WoH,  g_WoH);
    cudaGetSymbolAddress((void**)&W1H,  g_W1H);
    cudaGetSymbolAddress((void**)&W2H,  g_W2H);
    cudaGetSymbolAddress((void**)&x1,   g_x1);
    cudaGetSymbolAddress((void**)&bqkv, g_bqkv);

    const int SMEMG  = 3 * (128 * 72 + 64 * 136) * 2;      // 107520
    const int SMEMFL = (4 * 64 * 72 + 128 * 72) * 2;       // 55296
    cudaFuncSetAttribute(gemm_h,       cudaFuncAttributeMaxDynamicSharedMemorySize, SMEMG);
    cudaFuncSetAttribute(flash_kernel, cudaFuncAttributeMaxDynamicSharedMemorySize, SMEMFL);

    // 0) LN1 -> y (half)
    ln_kernel<<<S_LEN, 256>>>(x, ln1s, ln1b, y);

    // 1-6) weight converts (layout-preserving, K-major kept)
    cvt_kernel<<<1024, 256>>>(Wq, Wqkv, D_DIM, QKV_N, 0);
    cvt_kernel<<<1024, 256>>>(Wk, Wqkv, D_DIM, QKV_N, 1024);
    cvt_kernel<<<1024, 256>>>(Wv, Wqkv, D_DIM, QKV_N, 2048);
    cvt_kernel<<<1024, 256>>>(Wo, WoH,  D_DIM, D_DIM, 0);
    cvt_kernel<<<4096, 256>>>(W1, W1H,  FF_D,  FF_D,  0);
    cvt_kernel<<<4096, 256>>>(W2, W2H,  D_DIM, D_DIM, 0);

    // 7) bias concat (fp32)
    concat3_kernel<<<QKV_N / 256, 256>>>(bq, bk, bv, bqkv);

    // 8) fused QKV projection -> qkv (half)
    gemm_h<<<dim3(S_LEN / 128, QKV_N / 128), 256, SMEMG>>>(
        y, D_DIM, Wqkv, QKV_N, nullptr, qkv, QKV_N, D_DIM, bqkv, nullptr, EPI_BIAS);

    // 9-10) RoPE (1/sqrt(HD) folded into q)
    rope_kernel<<<dim3(S_LEN, NH), 32>>>(qkv,        QKV_N, 0.125f);
    rope_kernel<<<dim3(S_LEN, NH), 32>>>(qkv + 1024, QKV_N, 1.0f);

    // 11) fused attention -> o (half); V read in-place from qkv
    flash_kernel<<<dim3(S_LEN / 128, NH), 256, SMEMFL>>>(
        qkv, qkv + 1024, qkv + 2048, QKV_N, o);

    // 12) x1 = o @ Wo + bo + x  (fp32 out)
    gemm_h<<<dim3(S_LEN / 128, D_DIM / 128), 256, SMEMG>>>(
        o, D_DIM, WoH, D_DIM, x1, nullptr, D_DIM, D_DIM, bo, x, EPI_BIAS_RES);

    // 13) LN2 -> y (half)
    ln_kernel<<<S_LEN, 256>>>(x1, ln2s, ln2b, y);

    // 14) ffn = gelu(y @ W1 + b1) (half out)
    gemm_h<<<dim3(S_LEN / 128, FF_D / 128), 256, SMEMG>>>(
        y, D_DIM, W1H, FF_D, nullptr, ffn, FF_D, D_DIM, b1, nullptr, EPI_BIAS_GELU);

    // 15) out = ffn @ W2 + b2 + x1 (fp32 out)
    gemm_h<<<dim3(S_LEN / 128, D_DIM / 128), 256, SMEMG>>>(
        ffn, FF_D, W2H, D_DIM, out, nullptr, D_DIM, FF_D, b2, x1, EPI_BIAS_RES);
}